// round 1
// baseline (speedup 1.0000x reference)
#include <cuda_runtime.h>
#include <math.h>
#include <stdint.h>

#define DIM 768
#define TOK 4096          // B*N = 2*2048
#define SEQ 2048
#define NHEAD 12
#define HDIM 64
#define MLPD 3072

// ---------------- scratch (static device globals; no allocation) ----------------
__device__ float g_xn[TOK * DIM];
__device__ float g_qkv[TOK * 3 * DIM];
__device__ float g_attn[TOK * DIM];
__device__ float g_x1[TOK * DIM];
__device__ float g_h[TOK * DIM];
__device__ float g_h1[TOK * MLPD];

// ---------------- LayerNorm: one block (256 thr) per row of 768 ----------------
__global__ void ln_kernel(const float* __restrict__ x, const float* __restrict__ w,
                          const float* __restrict__ b, float* __restrict__ y) {
    const int row = blockIdx.x;
    const int tid = threadIdx.x;
    const float* xr = x + (size_t)row * DIM;
    float v0 = xr[tid], v1 = xr[tid + 256], v2 = xr[tid + 512];
    float s  = v0 + v1 + v2;
    float sq = v0 * v0 + v1 * v1 + v2 * v2;
    __shared__ float red0[8], red1[8];
    #pragma unroll
    for (int mm = 16; mm; mm >>= 1) {
        s  += __shfl_xor_sync(0xffffffffu, s,  mm);
        sq += __shfl_xor_sync(0xffffffffu, sq, mm);
    }
    const int wid = tid >> 5, lane = tid & 31;
    if (lane == 0) { red0[wid] = s; red1[wid] = sq; }
    __syncthreads();
    if (wid == 0) {
        s = red0[lane & 7]; sq = red1[lane & 7];
        #pragma unroll
        for (int mm = 4; mm; mm >>= 1) {
            s  += __shfl_xor_sync(0xffffffffu, s,  mm);
            sq += __shfl_xor_sync(0xffffffffu, sq, mm);
        }
        if (lane == 0) { red0[0] = s; red1[0] = sq; }
    }
    __syncthreads();
    s = red0[0]; sq = red1[0];
    const float mu  = s * (1.0f / DIM);
    const float var = sq * (1.0f / DIM) - mu * mu;
    const float r   = rsqrtf(var + 1e-5f);
    float* yr = y + (size_t)row * DIM;
    yr[tid]       = (v0 - mu) * r * w[tid]       + b[tid];
    yr[tid + 256] = (v1 - mu) * r * w[tid + 256] + b[tid + 256];
    yr[tid + 512] = (v2 - mu) * r * w[tid + 512] + b[tid + 512];
}

// ---------------- SGEMM 128x128, k-chunk 8, double-buffered, 8x8/thread ----------------
// EPI: 0 = bias, 1 = bias + residual, 2 = bias + exact GELU
template <int EPI>
__global__ __launch_bounds__(256, 2)
void sgemm_kernel(const float* __restrict__ A, const float* __restrict__ W,
                  const float* __restrict__ bias, const float* __restrict__ res,
                  float* __restrict__ C, int M, int N, int K) {
    __shared__ __align__(16) float As[2][8][128];
    __shared__ __align__(16) float Bs[2][8][132];   // pad vs STS conflicts
    const int tid = threadIdx.x;
    const int bm = blockIdx.y * 128, bn = blockIdx.x * 128;
    const int tx = tid & 15, ty = tid >> 4;
    const int arow = tid >> 1, acol = (tid & 1) * 4;
    const int brow = tid >> 5, bcol = (tid & 31) * 4;
    const float* Ap = A + (size_t)(bm + arow) * K + acol;
    const float* Bp = W + (size_t)brow * N + bn + bcol;

    float acc[8][8];
    #pragma unroll
    for (int i = 0; i < 8; ++i)
        #pragma unroll
        for (int j = 0; j < 8; ++j) acc[i][j] = 0.0f;

    // prologue: stage 0
    {
        float4 a  = *(const float4*)Ap;
        float4 bv = *(const float4*)Bp;
        As[0][acol + 0][arow] = a.x; As[0][acol + 1][arow] = a.y;
        As[0][acol + 2][arow] = a.z; As[0][acol + 3][arow] = a.w;
        *(float4*)&Bs[0][brow][bcol] = bv;
    }
    __syncthreads();

    const int nk = K >> 3;
    for (int kt = 0; kt < nk; ++kt) {
        const int cur = kt & 1;
        float4 a, bv;
        const bool more = (kt + 1 < nk);
        if (more) {
            a  = *(const float4*)(Ap + (kt + 1) * 8);
            bv = *(const float4*)(Bp + (size_t)(kt + 1) * 8 * N);
        }
        #pragma unroll
        for (int k = 0; k < 8; ++k) {
            float4 a0 = *(const float4*)&As[cur][k][ty * 8];
            float4 a1 = *(const float4*)&As[cur][k][ty * 8 + 4];
            float4 b0 = *(const float4*)&Bs[cur][k][tx * 8];
            float4 b1 = *(const float4*)&Bs[cur][k][tx * 8 + 4];
            float av[8] = {a0.x, a0.y, a0.z, a0.w, a1.x, a1.y, a1.z, a1.w};
            float bw[8] = {b0.x, b0.y, b0.z, b0.w, b1.x, b1.y, b1.z, b1.w};
            #pragma unroll
            for (int i = 0; i < 8; ++i)
                #pragma unroll
                for (int j = 0; j < 8; ++j)
                    acc[i][j] = fmaf(av[i], bw[j], acc[i][j]);
        }
        if (more) {
            const int nxt = cur ^ 1;
            As[nxt][acol + 0][arow] = a.x; As[nxt][acol + 1][arow] = a.y;
            As[nxt][acol + 2][arow] = a.z; As[nxt][acol + 3][arow] = a.w;
            *(float4*)&Bs[nxt][brow][bcol] = bv;
        }
        __syncthreads();
    }

    // epilogue
    #pragma unroll
    for (int i = 0; i < 8; ++i) {
        const int r = bm + ty * 8 + i;
        float* Crow = C + (size_t)r * N + bn + tx * 8;
        const float* bp = bias + bn + tx * 8;
        float v[8];
        #pragma unroll
        for (int j = 0; j < 8; ++j) v[j] = acc[i][j] + bp[j];
        if (EPI == 1) {
            const float* rp = res + (size_t)r * N + bn + tx * 8;
            float4 r0 = *(const float4*)rp;
            float4 r1 = *(const float4*)(rp + 4);
            v[0] += r0.x; v[1] += r0.y; v[2] += r0.z; v[3] += r0.w;
            v[4] += r1.x; v[5] += r1.y; v[6] += r1.z; v[7] += r1.w;
        }
        if (EPI == 2) {
            #pragma unroll
            for (int j = 0; j < 8; ++j)
                v[j] = 0.5f * v[j] * (1.0f + erff(v[j] * 0.70710678118654752f));
        }
        float4 o0 = make_float4(v[0], v[1], v[2], v[3]);
        float4 o1 = make_float4(v[4], v[5], v[6], v[7]);
        *(float4*)Crow = o0;
        *(float4*)(Crow + 4) = o1;
    }
}

// ---------------- Flash attention: 64-query tile per block, fp32, online softmax ----------------
// qkv row layout per token: [q(768) | k(768) | v(768)], head h at offset h*64.
__device__ __forceinline__ int sw_idx(int row, int col) {
    // 64-float rows, XOR-swizzle on 16B chunks using row bits [2:4]
    return row * 64 + ((((col >> 2) ^ ((row >> 2) & 7)) << 2) | (col & 3));
}

__global__ __launch_bounds__(256, 2)
void flash_kernel(const float* __restrict__ qkv, float* __restrict__ out) {
    __shared__ __align__(16) float Qs[64 * 64];
    __shared__ __align__(16) float Ks[64 * 64];   // reused as P after S-compute
    __shared__ __align__(16) float Vs[64 * 64];
    const int tid = threadIdx.x;
    const int pair = blockIdx.y;
    const int b = pair / NHEAD, h = pair % NHEAD;
    const int qt = blockIdx.x;
    const int tx = tid & 15, ty = tid >> 4;
    const int r0 = ty * 4, c0 = tx * 4;
    const size_t base = (size_t)b * SEQ * (3 * DIM);

    // load Q tile (plain layout; reads are lane-broadcast so no swizzle needed)
    #pragma unroll
    for (int it = 0; it < 4; ++it) {
        int f = tid + it * 256;
        int row = f >> 4, col4 = f & 15;
        float4 q = *(const float4*)&qkv[base + (size_t)(qt * 64 + row) * (3 * DIM) + h * 64 + col4 * 4];
        *(float4*)&Qs[row * 64 + col4 * 4] = q;
    }

    float mrow[4], lrow[4], o[4][4];
    #pragma unroll
    for (int i = 0; i < 4; ++i) {
        mrow[i] = -1e30f; lrow[i] = 0.0f;
        #pragma unroll
        for (int j = 0; j < 4; ++j) o[i][j] = 0.0f;
    }

    for (int kt = 0; kt < SEQ / 64; ++kt) {
        __syncthreads();  // previous iteration's P/V readers done
        #pragma unroll
        for (int it = 0; it < 4; ++it) {
            int f = tid + it * 256;
            int row = f >> 4, col4 = f & 15;
            size_t tokoff = base + (size_t)(kt * 64 + row) * (3 * DIM) + h * 64 + col4 * 4;
            float4 k = *(const float4*)&qkv[tokoff + DIM];
            float4 v = *(const float4*)&qkv[tokoff + 2 * DIM];
            *(float4*)&Ks[sw_idx(row, col4 * 4)] = k;
            *(float4*)&Vs[sw_idx(row, col4 * 4)] = v;
        }
        __syncthreads();

        // S[4][4] = Q(r0..r0+3) . K(c0..c0+3)
        float s[4][4];
        #pragma unroll
        for (int i = 0; i < 4; ++i)
            #pragma unroll
            for (int j = 0; j < 4; ++j) s[i][j] = 0.0f;
        #pragma unroll
        for (int d = 0; d < 64; d += 4) {
            float4 q4[4], k4[4];
            #pragma unroll
            for (int i = 0; i < 4; ++i) q4[i] = *(const float4*)&Qs[(r0 + i) * 64 + d];
            #pragma unroll
            for (int j = 0; j < 4; ++j) k4[j] = *(const float4*)&Ks[sw_idx(c0 + j, d)];
            #pragma unroll
            for (int i = 0; i < 4; ++i)
                #pragma unroll
                for (int j = 0; j < 4; ++j) {
                    s[i][j] = fmaf(q4[i].x, k4[j].x, s[i][j]);
                    s[i][j] = fmaf(q4[i].y, k4[j].y, s[i][j]);
                    s[i][j] = fmaf(q4[i].z, k4[j].z, s[i][j]);
                    s[i][j] = fmaf(q4[i].w, k4[j].w, s[i][j]);
                }
        }

        // online softmax (rows span the 16 tx-lanes; xor-shfl <16 stays in row group)
        float alpha[4];
        #pragma unroll
        for (int i = 0; i < 4; ++i) {
            float rm = -1e30f;
            #pragma unroll
            for (int j = 0; j < 4; ++j) { s[i][j] *= 0.125f; rm = fmaxf(rm, s[i][j]); }
            #pragma unroll
            for (int mm = 8; mm; mm >>= 1) rm = fmaxf(rm, __shfl_xor_sync(0xffffffffu, rm, mm));
            const float mn = fmaxf(mrow[i], rm);
            alpha[i] = __expf(mrow[i] - mn);
            float ps = 0.0f;
            #pragma unroll
            for (int j = 0; j < 4; ++j) { float p = __expf(s[i][j] - mn); s[i][j] = p; ps += p; }
            #pragma unroll
            for (int mm = 8; mm; mm >>= 1) ps += __shfl_xor_sync(0xffffffffu, ps, mm);
            lrow[i] = lrow[i] * alpha[i] + ps;
            mrow[i] = mn;
            #pragma unroll
            for (int j = 0; j < 4; ++j) o[i][j] *= alpha[i];
        }

        __syncthreads();  // everyone finished reading Ks
        #pragma unroll
        for (int i = 0; i < 4; ++i)
            #pragma unroll
            for (int j = 0; j < 4; ++j)
                Ks[sw_idx(r0 + i, c0 + j)] = s[i][j];
        __syncthreads();

        // O += P @ V
        #pragma unroll
        for (int k = 0; k < 64; k += 4) {
            float4 p4[4], v4[4];
            #pragma unroll
            for (int i = 0; i < 4; ++i) p4[i] = *(const float4*)&Ks[sw_idx(r0 + i, k)];
            #pragma unroll
            for (int kk = 0; kk < 4; ++kk) v4[kk] = *(const float4*)&Vs[sw_idx(k + kk, c0)];
            float pv[4][4] = {
                {p4[0].x, p4[0].y, p4[0].z, p4[0].w},
                {p4[1].x, p4[1].y, p4[1].z, p4[1].w},
                {p4[2].x, p4[2].y, p4[2].z, p4[2].w},
                {p4[3].x, p4[3].y, p4[3].z, p4[3].w}};
            float vv[4][4] = {
                {v4[0].x, v4[0].y, v4[0].z, v4[0].w},
                {v4[1].x, v4[1].y, v4[1].z, v4[1].w},
                {v4[2].x, v4[2].y, v4[2].z, v4[2].w},
                {v4[3].x, v4[3].y, v4[3].z, v4[3].w}};
            #pragma unroll
            for (int i = 0; i < 4; ++i)
                #pragma unroll
                for (int j = 0; j < 4; ++j) {
                    o[i][j] = fmaf(pv[i][0], vv[0][j], o[i][j]);
                    o[i][j] = fmaf(pv[i][1], vv[1][j], o[i][j]);
                    o[i][j] = fmaf(pv[i][2], vv[2][j], o[i][j]);
                    o[i][j] = fmaf(pv[i][3], vv[3][j], o[i][j]);
                }
        }
    }

    #pragma unroll
    for (int i = 0; i < 4; ++i) {
        const float inv = 1.0f / lrow[i];
        const int t = b * SEQ + qt * 64 + r0 + i;
        float4 r = make_float4(o[i][0] * inv, o[i][1] * inv, o[i][2] * inv, o[i][3] * inv);
        *(float4*)&out[(size_t)t * DIM + h * 64 + c0] = r;
    }
}

// ---------------- launch ----------------
static float* sym_addr(const void* sym) {
    void* p = nullptr;
    cudaGetSymbolAddress(&p, sym);
    return (float*)p;
}

extern "C" void kernel_launch(void* const* d_in, const int* in_sizes, int n_in,
                              void* d_out, int out_size) {
    const float* x     = (const float*)d_in[0];
    const float* ln1w  = (const float*)d_in[1];
    const float* ln1b  = (const float*)d_in[2];
    const float* qkvw  = (const float*)d_in[3];
    const float* qkvb  = (const float*)d_in[4];
    const float* projw = (const float*)d_in[5];
    const float* projb = (const float*)d_in[6];
    const float* ln2w  = (const float*)d_in[7];
    const float* ln2b  = (const float*)d_in[8];
    const float* lin1w = (const float*)d_in[9];
    const float* lin1b = (const float*)d_in[10];
    const float* lin2w = (const float*)d_in[11];
    const float* lin2b = (const float*)d_in[12];
    float* out = (float*)d_out;

    float* xn   = sym_addr(g_xn);
    float* qkvB = sym_addr(g_qkv);
    float* attn = sym_addr(g_attn);
    float* x1   = sym_addr(g_x1);
    float* hB   = sym_addr(g_h);
    float* h1   = sym_addr(g_h1);

    // 1. ln1
    ln_kernel<<<TOK, 256>>>(x, ln1w, ln1b, xn);
    // 2. qkv = xn @ qkv_w + b
    sgemm_kernel<0><<<dim3(3 * DIM / 128, TOK / 128), 256>>>(xn, qkvw, qkvb, nullptr, qkvB, TOK, 3 * DIM, DIM);
    // 3. attention
    flash_kernel<<<dim3(SEQ / 64, 2 * NHEAD), 256>>>(qkvB, attn);
    // 4. x1 = x + attn @ proj_w + b
    sgemm_kernel<1><<<dim3(DIM / 128, TOK / 128), 256>>>(attn, projw, projb, x, x1, TOK, DIM, DIM);
    // 5. ln2
    ln_kernel<<<TOK, 256>>>(x1, ln2w, ln2b, hB);
    // 6. h1 = gelu(h @ lin1_w + b)
    sgemm_kernel<2><<<dim3(MLPD / 128, TOK / 128), 256>>>(hB, lin1w, lin1b, nullptr, h1, TOK, MLPD, DIM);
    // 7. out = x1 + h1 @ lin2_w + b
    sgemm_kernel<1><<<dim3(DIM / 128, TOK / 128), 256>>>(h1, lin2w, lin2b, x1, out, TOK, DIM, MLPD);
}

// round 2
// speedup vs baseline: 1.4871x; 1.4871x over previous
#include <cuda_runtime.h>
#include <math.h>
#include <stdint.h>

#define DIM 768
#define TOK 4096          // B*N = 2*2048
#define SEQ 2048
#define NHEAD 12
#define HDIM 64
#define MLPD 3072

// ---------------- scratch (static device globals; no allocation) ----------------
__device__ float g_xn[TOK * DIM];
__device__ float g_qkv[TOK * 3 * DIM];
__device__ float g_attn[TOK * DIM];
__device__ float g_x1[TOK * DIM];
__device__ float g_h[TOK * DIM];
__device__ float g_h1[TOK * MLPD];

// ---------------- LayerNorm: one block (256 thr) per row of 768 ----------------
__global__ void ln_kernel(const float* __restrict__ x, const float* __restrict__ w,
                          const float* __restrict__ b, float* __restrict__ y) {
    const int row = blockIdx.x;
    const int tid = threadIdx.x;
    const float* xr = x + (size_t)row * DIM;
    float v0 = xr[tid], v1 = xr[tid + 256], v2 = xr[tid + 512];
    float s  = v0 + v1 + v2;
    float sq = v0 * v0 + v1 * v1 + v2 * v2;
    __shared__ float red0[8], red1[8];
    #pragma unroll
    for (int mm = 16; mm; mm >>= 1) {
        s  += __shfl_xor_sync(0xffffffffu, s,  mm);
        sq += __shfl_xor_sync(0xffffffffu, sq, mm);
    }
    const int wid = tid >> 5, lane = tid & 31;
    if (lane == 0) { red0[wid] = s; red1[wid] = sq; }
    __syncthreads();
    if (wid == 0) {
        s = red0[lane & 7]; sq = red1[lane & 7];
        #pragma unroll
        for (int mm = 4; mm; mm >>= 1) {
            s  += __shfl_xor_sync(0xffffffffu, s,  mm);
            sq += __shfl_xor_sync(0xffffffffu, sq, mm);
        }
        if (lane == 0) { red0[0] = s; red1[0] = sq; }
    }
    __syncthreads();
    s = red0[0]; sq = red1[0];
    const float mu  = s * (1.0f / DIM);
    const float var = sq * (1.0f / DIM) - mu * mu;
    const float r   = rsqrtf(var + 1e-5f);
    float* yr = y + (size_t)row * DIM;
    yr[tid]       = (v0 - mu) * r * w[tid]       + b[tid];
    yr[tid + 256] = (v1 - mu) * r * w[tid + 256] + b[tid + 256];
    yr[tid + 512] = (v2 - mu) * r * w[tid + 512] + b[tid + 512];
}

// ---------------- tf32 helpers ----------------
__device__ __forceinline__ uint32_t f2tf32(float f) {
    uint32_t u;
    asm("cvt.rna.tf32.f32 %0, %1;" : "=r"(u) : "f"(f));
    return u;
}

__device__ __forceinline__ void mma_tf32(float& c0, float& c1, float& c2, float& c3,
                                         uint32_t a0, uint32_t a1, uint32_t a2, uint32_t a3,
                                         uint32_t b0, uint32_t b1) {
    asm volatile(
        "mma.sync.aligned.m16n8k8.row.col.f32.tf32.tf32.f32 "
        "{%0,%1,%2,%3}, {%4,%5,%6,%7}, {%8,%9}, {%0,%1,%2,%3};"
        : "+f"(c0), "+f"(c1), "+f"(c2), "+f"(c3)
        : "r"(a0), "r"(a1), "r"(a2), "r"(a3), "r"(b0), "r"(b1));
}

// ---------------- tf32 tensor-core GEMM 128x128, BK=16, double-buffered ----------------
// 256 threads = 8 warps in a 2(m) x 4(n) grid; warp tile 64x32 (4 m-tiles x 4 n-tiles of m16n8k8).
// EPI: 0 = bias, 1 = bias + residual, 2 = bias + exact GELU
#define SM_PAD 132
template <int EPI>
__global__ __launch_bounds__(256, 2)
void tgemm_kernel(const float* __restrict__ A, const float* __restrict__ W,
                  const float* __restrict__ bias, const float* __restrict__ res,
                  float* __restrict__ C, int M, int N, int K) {
    __shared__ __align__(16) uint32_t As[2][16][SM_PAD];  // col-major: As[buf][k][m]
    __shared__ __align__(16) uint32_t Bs[2][16][SM_PAD];  // row-major: Bs[buf][k][n]

    const int tid = threadIdx.x;
    const int bm = blockIdx.y * 128, bn = blockIdx.x * 128;
    const int wid = tid >> 5, lane = tid & 31;
    const int warp_m = wid & 1, warp_n = wid >> 1;       // 2 x 4
    const int g = lane >> 2, tig = lane & 3;             // groupID / thread-in-group

    // global load indices
    const int ar = tid >> 2, ac4 = tid & 3;              // A: rows ar, ar+64; col4 ac4
    const int br = tid >> 5, bc = (tid & 31) * 4;        // B: rows br, br+8; cols bc..bc+3
    const float* Ap = A + (size_t)(bm + ar) * K + ac4 * 4;
    const float* Bp = W + (size_t)br * N + bn + bc;

    float acc[4][4][4];                                   // [m-tile][n-tile][c-frag]
    #pragma unroll
    for (int i = 0; i < 4; ++i)
        #pragma unroll
        for (int j = 0; j < 4; ++j)
            #pragma unroll
            for (int c = 0; c < 4; ++c) acc[i][j][c] = 0.0f;

    // ---- prologue: stage buffer 0
    {
        float4 a0 = *(const float4*)Ap;
        float4 a1 = *(const float4*)(Ap + (size_t)64 * K);
        float4 b0 = *(const float4*)Bp;
        float4 b1 = *(const float4*)(Bp + (size_t)8 * N);
        As[0][ac4 * 4 + 0][ar]      = f2tf32(a0.x);
        As[0][ac4 * 4 + 1][ar]      = f2tf32(a0.y);
        As[0][ac4 * 4 + 2][ar]      = f2tf32(a0.z);
        As[0][ac4 * 4 + 3][ar]      = f2tf32(a0.w);
        As[0][ac4 * 4 + 0][ar + 64] = f2tf32(a1.x);
        As[0][ac4 * 4 + 1][ar + 64] = f2tf32(a1.y);
        As[0][ac4 * 4 + 2][ar + 64] = f2tf32(a1.z);
        As[0][ac4 * 4 + 3][ar + 64] = f2tf32(a1.w);
        Bs[0][br][bc + 0]     = f2tf32(b0.x);
        Bs[0][br][bc + 1]     = f2tf32(b0.y);
        Bs[0][br][bc + 2]     = f2tf32(b0.z);
        Bs[0][br][bc + 3]     = f2tf32(b0.w);
        Bs[0][br + 8][bc + 0] = f2tf32(b1.x);
        Bs[0][br + 8][bc + 1] = f2tf32(b1.y);
        Bs[0][br + 8][bc + 2] = f2tf32(b1.z);
        Bs[0][br + 8][bc + 3] = f2tf32(b1.w);
    }
    __syncthreads();

    const int nk = K >> 4;    // BK = 16
    for (int kt = 0; kt < nk; ++kt) {
        const int cur = kt & 1;
        float4 pa0, pa1, pb0, pb1;
        const bool more = (kt + 1 < nk);
        if (more) {
            pa0 = *(const float4*)(Ap + (kt + 1) * 16);
            pa1 = *(const float4*)(Ap + (size_t)64 * K + (kt + 1) * 16);
            pb0 = *(const float4*)(Bp + (size_t)(kt + 1) * 16 * N);
            pb1 = *(const float4*)(Bp + (size_t)((kt + 1) * 16 + 8) * N);
        }

        #pragma unroll
        for (int ks = 0; ks < 16; ks += 8) {
            uint32_t af[4][4], bf[4][2];
            #pragma unroll
            for (int i = 0; i < 4; ++i) {
                const int mb = warp_m * 64 + i * 16;
                af[i][0] = As[cur][ks + tig][mb + g];
                af[i][1] = As[cur][ks + tig][mb + g + 8];
                af[i][2] = As[cur][ks + tig + 4][mb + g];
                af[i][3] = As[cur][ks + tig + 4][mb + g + 8];
            }
            #pragma unroll
            for (int j = 0; j < 4; ++j) {
                const int nb = warp_n * 32 + j * 8;
                bf[j][0] = Bs[cur][ks + tig][nb + g];
                bf[j][1] = Bs[cur][ks + tig + 4][nb + g];
            }
            #pragma unroll
            for (int i = 0; i < 4; ++i)
                #pragma unroll
                for (int j = 0; j < 4; ++j)
                    mma_tf32(acc[i][j][0], acc[i][j][1], acc[i][j][2], acc[i][j][3],
                             af[i][0], af[i][1], af[i][2], af[i][3],
                             bf[j][0], bf[j][1]);
        }

        if (more) {
            const int nxt = cur ^ 1;
            As[nxt][ac4 * 4 + 0][ar]      = f2tf32(pa0.x);
            As[nxt][ac4 * 4 + 1][ar]      = f2tf32(pa0.y);
            As[nxt][ac4 * 4 + 2][ar]      = f2tf32(pa0.z);
            As[nxt][ac4 * 4 + 3][ar]      = f2tf32(pa0.w);
            As[nxt][ac4 * 4 + 0][ar + 64] = f2tf32(pa1.x);
            As[nxt][ac4 * 4 + 1][ar + 64] = f2tf32(pa1.y);
            As[nxt][ac4 * 4 + 2][ar + 64] = f2tf32(pa1.z);
            As[nxt][ac4 * 4 + 3][ar + 64] = f2tf32(pa1.w);
            Bs[nxt][br][bc + 0]     = f2tf32(pb0.x);
            Bs[nxt][br][bc + 1]     = f2tf32(pb0.y);
            Bs[nxt][br][bc + 2]     = f2tf32(pb0.z);
            Bs[nxt][br][bc + 3]     = f2tf32(pb0.w);
            Bs[nxt][br + 8][bc + 0] = f2tf32(pb1.x);
            Bs[nxt][br + 8][bc + 1] = f2tf32(pb1.y);
            Bs[nxt][br + 8][bc + 2] = f2tf32(pb1.z);
            Bs[nxt][br + 8][bc + 3] = f2tf32(pb1.w);
        }
        __syncthreads();
    }

    // ---- epilogue: each thread owns rows {g, g+8} per m-tile, col pair 2*tig per n-tile
    #pragma unroll
    for (int i = 0; i < 4; ++i) {
        #pragma unroll
        for (int half = 0; half < 2; ++half) {
            const int r = bm + warp_m * 64 + i * 16 + g + half * 8;
            float* Crow = C + (size_t)r * N;
            const float* Rrow = (EPI == 1) ? (res + (size_t)r * N) : nullptr;
            #pragma unroll
            for (int j = 0; j < 4; ++j) {
                const int col = bn + warp_n * 32 + j * 8 + tig * 2;
                float v0 = acc[i][j][half * 2 + 0] + bias[col];
                float v1 = acc[i][j][half * 2 + 1] + bias[col + 1];
                if (EPI == 1) {
                    v0 += Rrow[col];
                    v1 += Rrow[col + 1];
                }
                if (EPI == 2) {
                    v0 = 0.5f * v0 * (1.0f + erff(v0 * 0.70710678118654752f));
                    v1 = 0.5f * v1 * (1.0f + erff(v1 * 0.70710678118654752f));
                }
                *(float2*)&Crow[col] = make_float2(v0, v1);
            }
        }
    }
}

// ---------------- Flash attention: 64-query tile per block, fp32, online softmax ----------------
__device__ __forceinline__ int sw_idx(int row, int col) {
    return row * 64 + ((((col >> 2) ^ ((row >> 2) & 7)) << 2) | (col & 3));
}

__global__ __launch_bounds__(256, 2)
void flash_kernel(const float* __restrict__ qkv, float* __restrict__ out) {
    __shared__ __align__(16) float Qs[64 * 64];
    __shared__ __align__(16) float Ks[64 * 64];   // reused as P after S-compute
    __shared__ __align__(16) float Vs[64 * 64];
    const int tid = threadIdx.x;
    const int pair = blockIdx.y;
    const int b = pair / NHEAD, h = pair % NHEAD;
    const int qt = blockIdx.x;
    const int tx = tid & 15, ty = tid >> 4;
    const int r0 = ty * 4, c0 = tx * 4;
    const size_t base = (size_t)b * SEQ * (3 * DIM);

    #pragma unroll
    for (int it = 0; it < 4; ++it) {
        int f = tid + it * 256;
        int row = f >> 4, col4 = f & 15;
        float4 q = *(const float4*)&qkv[base + (size_t)(qt * 64 + row) * (3 * DIM) + h * 64 + col4 * 4];
        *(float4*)&Qs[row * 64 + col4 * 4] = q;
    }

    float mrow[4], lrow[4], o[4][4];
    #pragma unroll
    for (int i = 0; i < 4; ++i) {
        mrow[i] = -1e30f; lrow[i] = 0.0f;
        #pragma unroll
        for (int j = 0; j < 4; ++j) o[i][j] = 0.0f;
    }

    for (int kt = 0; kt < SEQ / 64; ++kt) {
        __syncthreads();
        #pragma unroll
        for (int it = 0; it < 4; ++it) {
            int f = tid + it * 256;
            int row = f >> 4, col4 = f & 15;
            size_t tokoff = base + (size_t)(kt * 64 + row) * (3 * DIM) + h * 64 + col4 * 4;
            float4 k = *(const float4*)&qkv[tokoff + DIM];
            float4 v = *(const float4*)&qkv[tokoff + 2 * DIM];
            *(float4*)&Ks[sw_idx(row, col4 * 4)] = k;
            *(float4*)&Vs[sw_idx(row, col4 * 4)] = v;
        }
        __syncthreads();

        float s[4][4];
        #pragma unroll
        for (int i = 0; i < 4; ++i)
            #pragma unroll
            for (int j = 0; j < 4; ++j) s[i][j] = 0.0f;
        #pragma unroll
        for (int d = 0; d < 64; d += 4) {
            float4 q4[4], k4[4];
            #pragma unroll
            for (int i = 0; i < 4; ++i) q4[i] = *(const float4*)&Qs[(r0 + i) * 64 + d];
            #pragma unroll
            for (int j = 0; j < 4; ++j) k4[j] = *(const float4*)&Ks[sw_idx(c0 + j, d)];
            #pragma unroll
            for (int i = 0; i < 4; ++i)
                #pragma unroll
                for (int j = 0; j < 4; ++j) {
                    s[i][j] = fmaf(q4[i].x, k4[j].x, s[i][j]);
                    s[i][j] = fmaf(q4[i].y, k4[j].y, s[i][j]);
                    s[i][j] = fmaf(q4[i].z, k4[j].z, s[i][j]);
                    s[i][j] = fmaf(q4[i].w, k4[j].w, s[i][j]);
                }
        }

        float alpha[4];
        #pragma unroll
        for (int i = 0; i < 4; ++i) {
            float rm = -1e30f;
            #pragma unroll
            for (int j = 0; j < 4; ++j) { s[i][j] *= 0.125f; rm = fmaxf(rm, s[i][j]); }
            #pragma unroll
            for (int mm = 8; mm; mm >>= 1) rm = fmaxf(rm, __shfl_xor_sync(0xffffffffu, rm, mm));
            const float mn = fmaxf(mrow[i], rm);
            alpha[i] = __expf(mrow[i] - mn);
            float ps = 0.0f;
            #pragma unroll
            for (int j = 0; j < 4; ++j) { float p = __expf(s[i][j] - mn); s[i][j] = p; ps += p; }
            #pragma unroll
            for (int mm = 8; mm; mm >>= 1) ps += __shfl_xor_sync(0xffffffffu, ps, mm);
            lrow[i] = lrow[i] * alpha[i] + ps;
            mrow[i] = mn;
            #pragma unroll
            for (int j = 0; j < 4; ++j) o[i][j] *= alpha[i];
        }

        __syncthreads();
        #pragma unroll
        for (int i = 0; i < 4; ++i)
            #pragma unroll
            for (int j = 0; j < 4; ++j)
                Ks[sw_idx(r0 + i, c0 + j)] = s[i][j];
        __syncthreads();

        #pragma unroll
        for (int k = 0; k < 64; k += 4) {
            float4 p4[4], v4[4];
            #pragma unroll
            for (int i = 0; i < 4; ++i) p4[i] = *(const float4*)&Ks[sw_idx(r0 + i, k)];
            #pragma unroll
            for (int kk = 0; kk < 4; ++kk) v4[kk] = *(const float4*)&Vs[sw_idx(k + kk, c0)];
            float pv[4][4] = {
                {p4[0].x, p4[0].y, p4[0].z, p4[0].w},
                {p4[1].x, p4[1].y, p4[1].z, p4[1].w},
                {p4[2].x, p4[2].y, p4[2].z, p4[2].w},
                {p4[3].x, p4[3].y, p4[3].z, p4[3].w}};
            float vv[4][4] = {
                {v4[0].x, v4[0].y, v4[0].z, v4[0].w},
                {v4[1].x, v4[1].y, v4[1].z, v4[1].w},
                {v4[2].x, v4[2].y, v4[2].z, v4[2].w},
                {v4[3].x, v4[3].y, v4[3].z, v4[3].w}};
            #pragma unroll
            for (int i = 0; i < 4; ++i)
                #pragma unroll
                for (int j = 0; j < 4; ++j) {
                    o[i][j] = fmaf(pv[i][0], vv[0][j], o[i][j]);
                    o[i][j] = fmaf(pv[i][1], vv[1][j], o[i][j]);
                    o[i][j] = fmaf(pv[i][2], vv[2][j], o[i][j]);
                    o[i][j] = fmaf(pv[i][3], vv[3][j], o[i][j]);
                }
        }
    }

    #pragma unroll
    for (int i = 0; i < 4; ++i) {
        const float inv = 1.0f / lrow[i];
        const int t = b * SEQ + qt * 64 + r0 + i;
        float4 r = make_float4(o[i][0] * inv, o[i][1] * inv, o[i][2] * inv, o[i][3] * inv);
        *(float4*)&out[(size_t)t * DIM + h * 64 + c0] = r;
    }
}

// ---------------- launch ----------------
static float* sym_addr(const void* sym) {
    void* p = nullptr;
    cudaGetSymbolAddress(&p, sym);
    return (float*)p;
}

extern "C" void kernel_launch(void* const* d_in, const int* in_sizes, int n_in,
                              void* d_out, int out_size) {
    const float* x     = (const float*)d_in[0];
    const float* ln1w  = (const float*)d_in[1];
    const float* ln1b  = (const float*)d_in[2];
    const float* qkvw  = (const float*)d_in[3];
    const float* qkvb  = (const float*)d_in[4];
    const float* projw = (const float*)d_in[5];
    const float* projb = (const float*)d_in[6];
    const float* ln2w  = (const float*)d_in[7];
    const float* ln2b  = (const float*)d_in[8];
    const float* lin1w = (const float*)d_in[9];
    const float* lin1b = (const float*)d_in[10];
    const float* lin2w = (const float*)d_in[11];
    const float* lin2b = (const float*)d_in[12];
    float* out = (float*)d_out;

    float* xn   = sym_addr(g_xn);
    float* qkvB = sym_addr(g_qkv);
    float* attn = sym_addr(g_attn);
    float* x1   = sym_addr(g_x1);
    float* hB   = sym_addr(g_h);
    float* h1   = sym_addr(g_h1);

    // 1. ln1
    ln_kernel<<<TOK, 256>>>(x, ln1w, ln1b, xn);
    // 2. qkv = xn @ qkv_w + b  (tf32 TC)
    tgemm_kernel<0><<<dim3(3 * DIM / 128, TOK / 128), 256>>>(xn, qkvw, qkvb, nullptr, qkvB, TOK, 3 * DIM, DIM);
    // 3. attention
    flash_kernel<<<dim3(SEQ / 64, 2 * NHEAD), 256>>>(qkvB, attn);
    // 4. x1 = x + attn @ proj_w + b  (tf32 TC)
    tgemm_kernel<1><<<dim3(DIM / 128, TOK / 128), 256>>>(attn, projw, projb, x, x1, TOK, DIM, DIM);
    // 5. ln2
    ln_kernel<<<TOK, 256>>>(x1, ln2w, ln2b, hB);
    // 6. h1 = gelu(h @ lin1_w + b)  (tf32 TC)
    tgemm_kernel<2><<<dim3(MLPD / 128, TOK / 128), 256>>>(hB, lin1w, lin1b, nullptr, h1, TOK, MLPD, DIM);
    // 7. out = x1 + h1 @ lin2_w + b  (tf32 TC)
    tgemm_kernel<1><<<dim3(DIM / 128, TOK / 128), 256>>>(h1, lin2w, lin2b, x1, out, TOK, DIM, MLPD);
}

// round 4
// speedup vs baseline: 2.3369x; 1.5715x over previous
#include <cuda_runtime.h>
#include <math.h>
#include <stdint.h>

#define DIM 768
#define TOK 4096          // B*N = 2*2048
#define SEQ 2048
#define NHEAD 12
#define HDIM 64
#define MLPD 3072

// ---------------- scratch (static device globals; no allocation) ----------------
__device__ float g_xn[TOK * DIM];
__device__ float g_qkv[TOK * 3 * DIM];
__device__ float g_attn[TOK * DIM];
__device__ float g_x1[TOK * DIM];
__device__ float g_h[TOK * DIM];
__device__ float g_h1[TOK * MLPD];

// ---------------- LayerNorm: one block (256 thr) per row of 768 ----------------
__global__ void ln_kernel(const float* __restrict__ x, const float* __restrict__ w,
                          const float* __restrict__ b, float* __restrict__ y) {
    const int row = blockIdx.x;
    const int tid = threadIdx.x;
    const float* xr = x + (size_t)row * DIM;
    float v0 = xr[tid], v1 = xr[tid + 256], v2 = xr[tid + 512];
    float s  = v0 + v1 + v2;
    float sq = v0 * v0 + v1 * v1 + v2 * v2;
    __shared__ float red0[8], red1[8];
    #pragma unroll
    for (int mm = 16; mm; mm >>= 1) {
        s  += __shfl_xor_sync(0xffffffffu, s,  mm);
        sq += __shfl_xor_sync(0xffffffffu, sq, mm);
    }
    const int wid = tid >> 5, lane = tid & 31;
    if (lane == 0) { red0[wid] = s; red1[wid] = sq; }
    __syncthreads();
    if (wid == 0) {
        s = red0[lane & 7]; sq = red1[lane & 7];
        #pragma unroll
        for (int mm = 4; mm; mm >>= 1) {
            s  += __shfl_xor_sync(0xffffffffu, s,  mm);
            sq += __shfl_xor_sync(0xffffffffu, sq, mm);
        }
        if (lane == 0) { red0[0] = s; red1[0] = sq; }
    }
    __syncthreads();
    s = red0[0]; sq = red1[0];
    const float mu  = s * (1.0f / DIM);
    const float var = sq * (1.0f / DIM) - mu * mu;
    const float r   = rsqrtf(var + 1e-5f);
    float* yr = y + (size_t)row * DIM;
    yr[tid]       = (v0 - mu) * r * w[tid]       + b[tid];
    yr[tid + 256] = (v1 - mu) * r * w[tid + 256] + b[tid + 256];
    yr[tid + 512] = (v2 - mu) * r * w[tid + 512] + b[tid + 512];
}

// ---------------- tf32 helpers ----------------
__device__ __forceinline__ uint32_t f2tf32(float f) {
    uint32_t u;
    asm("cvt.rna.tf32.f32 %0, %1;" : "=r"(u) : "f"(f));
    return u;
}

__device__ __forceinline__ void mma_tf32(float& c0, float& c1, float& c2, float& c3,
                                         uint32_t a0, uint32_t a1, uint32_t a2, uint32_t a3,
                                         uint32_t b0, uint32_t b1) {
    asm volatile(
        "mma.sync.aligned.m16n8k8.row.col.f32.tf32.tf32.f32 "
        "{%0,%1,%2,%3}, {%4,%5,%6,%7}, {%8,%9}, {%0,%1,%2,%3};"
        : "+f"(c0), "+f"(c1), "+f"(c2), "+f"(c3)
        : "r"(a0), "r"(a1), "r"(a2), "r"(a3), "r"(b0), "r"(b1));
}

// ---------------- tf32 tensor-core GEMM 128x128, BK=16, double-buffered ----------------
// 256 threads = 8 warps in a 2(m) x 4(n) grid; warp tile 64x32 (4 m-tiles x 4 n-tiles of m16n8k8).
// EPI: 0 = bias, 1 = bias + residual, 2 = bias + exact GELU
#define SM_PAD 132
template <int EPI>
__global__ __launch_bounds__(256, 2)
void tgemm_kernel(const float* __restrict__ A, const float* __restrict__ W,
                  const float* __restrict__ bias, const float* __restrict__ res,
                  float* __restrict__ C, int M, int N, int K) {
    __shared__ __align__(16) uint32_t As[2][16][SM_PAD];  // col-major: As[buf][k][m]
    __shared__ __align__(16) uint32_t Bs[2][16][SM_PAD];  // row-major: Bs[buf][k][n]

    const int tid = threadIdx.x;
    const int bm = blockIdx.y * 128, bn = blockIdx.x * 128;
    const int wid = tid >> 5, lane = tid & 31;
    const int warp_m = wid & 1, warp_n = wid >> 1;       // 2 x 4
    const int g = lane >> 2, tig = lane & 3;             // groupID / thread-in-group

    const int ar = tid >> 2, ac4 = tid & 3;
    const int br = tid >> 5, bc = (tid & 31) * 4;
    const float* Ap = A + (size_t)(bm + ar) * K + ac4 * 4;
    const float* Bp = W + (size_t)br * N + bn + bc;

    float acc[4][4][4];
    #pragma unroll
    for (int i = 0; i < 4; ++i)
        #pragma unroll
        for (int j = 0; j < 4; ++j)
            #pragma unroll
            for (int c = 0; c < 4; ++c) acc[i][j][c] = 0.0f;

    {
        float4 a0 = *(const float4*)Ap;
        float4 a1 = *(const float4*)(Ap + (size_t)64 * K);
        float4 b0 = *(const float4*)Bp;
        float4 b1 = *(const float4*)(Bp + (size_t)8 * N);
        As[0][ac4 * 4 + 0][ar]      = f2tf32(a0.x);
        As[0][ac4 * 4 + 1][ar]      = f2tf32(a0.y);
        As[0][ac4 * 4 + 2][ar]      = f2tf32(a0.z);
        As[0][ac4 * 4 + 3][ar]      = f2tf32(a0.w);
        As[0][ac4 * 4 + 0][ar + 64] = f2tf32(a1.x);
        As[0][ac4 * 4 + 1][ar + 64] = f2tf32(a1.y);
        As[0][ac4 * 4 + 2][ar + 64] = f2tf32(a1.z);
        As[0][ac4 * 4 + 3][ar + 64] = f2tf32(a1.w);
        Bs[0][br][bc + 0]     = f2tf32(b0.x);
        Bs[0][br][bc + 1]     = f2tf32(b0.y);
        Bs[0][br][bc + 2]     = f2tf32(b0.z);
        Bs[0][br][bc + 3]     = f2tf32(b0.w);
        Bs[0][br + 8][bc + 0] = f2tf32(b1.x);
        Bs[0][br + 8][bc + 1] = f2tf32(b1.y);
        Bs[0][br + 8][bc + 2] = f2tf32(b1.z);
        Bs[0][br + 8][bc + 3] = f2tf32(b1.w);
    }
    __syncthreads();

    const int nk = K >> 4;    // BK = 16
    for (int kt = 0; kt < nk; ++kt) {
        const int cur = kt & 1;
        float4 pa0, pa1, pb0, pb1;
        const bool more = (kt + 1 < nk);
        if (more) {
            pa0 = *(const float4*)(Ap + (kt + 1) * 16);
            pa1 = *(const float4*)(Ap + (size_t)64 * K + (kt + 1) * 16);
            pb0 = *(const float4*)(Bp + (size_t)(kt + 1) * 16 * N);
            pb1 = *(const float4*)(Bp + (size_t)((kt + 1) * 16 + 8) * N);
        }

        #pragma unroll
        for (int ks = 0; ks < 16; ks += 8) {
            uint32_t af[4][4], bf[4][2];
            #pragma unroll
            for (int i = 0; i < 4; ++i) {
                const int mb = warp_m * 64 + i * 16;
                af[i][0] = As[cur][ks + tig][mb + g];
                af[i][1] = As[cur][ks + tig][mb + g + 8];
                af[i][2] = As[cur][ks + tig + 4][mb + g];
                af[i][3] = As[cur][ks + tig + 4][mb + g + 8];
            }
            #pragma unroll
            for (int j = 0; j < 4; ++j) {
                const int nb = warp_n * 32 + j * 8;
                bf[j][0] = Bs[cur][ks + tig][nb + g];
                bf[j][1] = Bs[cur][ks + tig + 4][nb + g];
            }
            #pragma unroll
            for (int i = 0; i < 4; ++i)
                #pragma unroll
                for (int j = 0; j < 4; ++j)
                    mma_tf32(acc[i][j][0], acc[i][j][1], acc[i][j][2], acc[i][j][3],
                             af[i][0], af[i][1], af[i][2], af[i][3],
                             bf[j][0], bf[j][1]);
        }

        if (more) {
            const int nxt = cur ^ 1;
            As[nxt][ac4 * 4 + 0][ar]      = f2tf32(pa0.x);
            As[nxt][ac4 * 4 + 1][ar]      = f2tf32(pa0.y);
            As[nxt][ac4 * 4 + 2][ar]      = f2tf32(pa0.z);
            As[nxt][ac4 * 4 + 3][ar]      = f2tf32(pa0.w);
            As[nxt][ac4 * 4 + 0][ar + 64] = f2tf32(pa1.x);
            As[nxt][ac4 * 4 + 1][ar + 64] = f2tf32(pa1.y);
            As[nxt][ac4 * 4 + 2][ar + 64] = f2tf32(pa1.z);
            As[nxt][ac4 * 4 + 3][ar + 64] = f2tf32(pa1.w);
            Bs[nxt][br][bc + 0]     = f2tf32(pb0.x);
            Bs[nxt][br][bc + 1]     = f2tf32(pb0.y);
            Bs[nxt][br][bc + 2]     = f2tf32(pb0.z);
            Bs[nxt][br][bc + 3]     = f2tf32(pb0.w);
            Bs[nxt][br + 8][bc + 0] = f2tf32(pb1.x);
            Bs[nxt][br + 8][bc + 1] = f2tf32(pb1.y);
            Bs[nxt][br + 8][bc + 2] = f2tf32(pb1.z);
            Bs[nxt][br + 8][bc + 3] = f2tf32(pb1.w);
        }
        __syncthreads();
    }

    #pragma unroll
    for (int i = 0; i < 4; ++i) {
        #pragma unroll
        for (int half = 0; half < 2; ++half) {
            const int r = bm + warp_m * 64 + i * 16 + g + half * 8;
            float* Crow = C + (size_t)r * N;
            const float* Rrow = (EPI == 1) ? (res + (size_t)r * N) : nullptr;
            #pragma unroll
            for (int j = 0; j < 4; ++j) {
                const int col = bn + warp_n * 32 + j * 8 + tig * 2;
                float v0 = acc[i][j][half * 2 + 0] + bias[col];
                float v1 = acc[i][j][half * 2 + 1] + bias[col + 1];
                if (EPI == 1) {
                    v0 += Rrow[col];
                    v1 += Rrow[col + 1];
                }
                if (EPI == 2) {
                    v0 = 0.5f * v0 * (1.0f + erff(v0 * 0.70710678118654752f));
                    v1 = 0.5f * v1 * (1.0f + erff(v1 * 0.70710678118654752f));
                }
                *(float2*)&Crow[col] = make_float2(v0, v1);
            }
        }
    }
}

// ---------------- tf32 tensor-core flash attention ----------------
// 64-query tile per block, 128 threads (4 warps; warp w owns q rows [w*16, w*16+16)).
// KV tiles of 64. S = Q.K^T and O += P.V both via m16n8k8 tf32 mma.
// Smem pitches chosen for conflict-free fragment reads:
//   Q/K/P pitch 68 (bank pattern g*4+tig, distinct mod 32)
//   V pitch 72     (bank pattern tig*8+g, distinct mod 32)
#define QP 68
#define VP 72
#define FLASH_SMEM_U32 (64 * QP /*Q*/ + 64 * QP /*K*/ + 64 * VP /*V*/ + 64 * QP /*P*/)

__global__ __launch_bounds__(128, 3)
void flash_tc_kernel(const float* __restrict__ qkv, float* __restrict__ out) {
    extern __shared__ uint32_t sm[];
    uint32_t* Qs = sm;                 // 64 x QP
    uint32_t* Ks = Qs + 64 * QP;       // 64 x QP
    uint32_t* Vs = Ks + 64 * QP;       // 64 x VP
    uint32_t* Ps = Vs + 64 * VP;       // 64 x QP

    const int tid = threadIdx.x;
    const int wid = tid >> 5, lane = tid & 31;
    const int g = lane >> 2, tig = lane & 3;
    const int bh = blockIdx.y;
    const int b = bh / NHEAD, h = bh % NHEAD;
    const int q0 = blockIdx.x * 64;
    const int r0 = wid * 16;                   // warp's row base within the q tile
    const size_t base = (size_t)b * SEQ * (3 * DIM);

    // ---- load Q tile (64 x 64), convert to tf32
    #pragma unroll
    for (int it = 0; it < 8; ++it) {
        const int f = tid + it * 128;
        const int row = f >> 4, c4 = f & 15;
        float4 q = *(const float4*)&qkv[base + (size_t)(q0 + row) * (3 * DIM) + h * 64 + c4 * 4];
        uint32_t* p = &Qs[row * QP + c4 * 4];
        p[0] = f2tf32(q.x); p[1] = f2tf32(q.y); p[2] = f2tf32(q.z); p[3] = f2tf32(q.w);
    }

    float m0 = -1e30f, m1 = -1e30f, l0 = 0.0f, l1 = 0.0f;
    float oacc[8][4];
    #pragma unroll
    for (int j = 0; j < 8; ++j)
        #pragma unroll
        for (int c = 0; c < 4; ++c) oacc[j][c] = 0.0f;

    for (int kt = 0; kt < SEQ / 64; ++kt) {
        __syncthreads();   // all warps done with previous K/V
        #pragma unroll
        for (int it = 0; it < 8; ++it) {
            const int f = tid + it * 128;
            const int row = f >> 4, c4 = f & 15;
            const size_t off = base + (size_t)(kt * 64 + row) * (3 * DIM) + h * 64 + c4 * 4;
            float4 k = *(const float4*)&qkv[off + DIM];
            float4 v = *(const float4*)&qkv[off + 2 * DIM];
            uint32_t* pk = &Ks[row * QP + c4 * 4];
            pk[0] = f2tf32(k.x); pk[1] = f2tf32(k.y); pk[2] = f2tf32(k.z); pk[3] = f2tf32(k.w);
            uint32_t* pv = &Vs[row * VP + c4 * 4];
            pv[0] = f2tf32(v.x); pv[1] = f2tf32(v.y); pv[2] = f2tf32(v.z); pv[3] = f2tf32(v.w);
        }
        __syncthreads();

        // ---- S = Q . K^T  (warp strip 16 x 64; 8 n-tiles x 8 k-steps)
        float sacc[8][4];
        #pragma unroll
        for (int j = 0; j < 8; ++j)
            #pragma unroll
            for (int c = 0; c < 4; ++c) sacc[j][c] = 0.0f;

        #pragma unroll
        for (int ks = 0; ks < 64; ks += 8) {
            const uint32_t a0 = Qs[(r0 + g) * QP + ks + tig];
            const uint32_t a1 = Qs[(r0 + g + 8) * QP + ks + tig];
            const uint32_t a2 = Qs[(r0 + g) * QP + ks + tig + 4];
            const uint32_t a3 = Qs[(r0 + g + 8) * QP + ks + tig + 4];
            #pragma unroll
            for (int j = 0; j < 8; ++j) {
                const uint32_t b0 = Ks[(j * 8 + g) * QP + ks + tig];
                const uint32_t b1 = Ks[(j * 8 + g) * QP + ks + tig + 4];
                mma_tf32(sacc[j][0], sacc[j][1], sacc[j][2], sacc[j][3],
                         a0, a1, a2, a3, b0, b1);
            }
        }

        // ---- online softmax (rows g and g+8 of warp strip)
        float rm0 = -1e30f, rm1 = -1e30f;
        #pragma unroll
        for (int j = 0; j < 8; ++j) {
            sacc[j][0] *= 0.125f; sacc[j][1] *= 0.125f;
            sacc[j][2] *= 0.125f; sacc[j][3] *= 0.125f;
            rm0 = fmaxf(rm0, fmaxf(sacc[j][0], sacc[j][1]));
            rm1 = fmaxf(rm1, fmaxf(sacc[j][2], sacc[j][3]));
        }
        rm0 = fmaxf(rm0, __shfl_xor_sync(0xffffffffu, rm0, 1));
        rm0 = fmaxf(rm0, __shfl_xor_sync(0xffffffffu, rm0, 2));
        rm1 = fmaxf(rm1, __shfl_xor_sync(0xffffffffu, rm1, 1));
        rm1 = fmaxf(rm1, __shfl_xor_sync(0xffffffffu, rm1, 2));

        const float mn0 = fmaxf(m0, rm0);
        const float mn1 = fmaxf(m1, rm1);
        const float alpha0 = __expf(m0 - mn0);
        const float alpha1 = __expf(m1 - mn1);
        m0 = mn0; m1 = mn1;

        float ps0 = 0.0f, ps1 = 0.0f;
        #pragma unroll
        for (int j = 0; j < 8; ++j) {
            sacc[j][0] = __expf(sacc[j][0] - mn0);
            sacc[j][1] = __expf(sacc[j][1] - mn0);
            sacc[j][2] = __expf(sacc[j][2] - mn1);
            sacc[j][3] = __expf(sacc[j][3] - mn1);
            ps0 += sacc[j][0] + sacc[j][1];
            ps1 += sacc[j][2] + sacc[j][3];
        }
        ps0 += __shfl_xor_sync(0xffffffffu, ps0, 1);
        ps0 += __shfl_xor_sync(0xffffffffu, ps0, 2);
        ps1 += __shfl_xor_sync(0xffffffffu, ps1, 1);
        ps1 += __shfl_xor_sync(0xffffffffu, ps1, 2);
        l0 = l0 * alpha0 + ps0;
        l1 = l1 * alpha1 + ps1;

        #pragma unroll
        for (int j = 0; j < 8; ++j) {
            oacc[j][0] *= alpha0; oacc[j][1] *= alpha0;
            oacc[j][2] *= alpha1; oacc[j][3] *= alpha1;
        }

        // ---- write P (C-layout -> smem, tf32), per-warp private region
        #pragma unroll
        for (int j = 0; j < 8; ++j) {
            const int col = j * 8 + 2 * tig;
            Ps[(r0 + g) * QP + col]         = f2tf32(sacc[j][0]);
            Ps[(r0 + g) * QP + col + 1]     = f2tf32(sacc[j][1]);
            Ps[(r0 + g + 8) * QP + col]     = f2tf32(sacc[j][2]);
            Ps[(r0 + g + 8) * QP + col + 1] = f2tf32(sacc[j][3]);
        }
        __syncwarp();

        // ---- O += P . V   (A = P[16 x 64kv], B(k=kv, n=d) = V[kv][d])
        #pragma unroll
        for (int ks = 0; ks < 64; ks += 8) {
            const uint32_t a0 = Ps[(r0 + g) * QP + ks + tig];
            const uint32_t a1 = Ps[(r0 + g + 8) * QP + ks + tig];
            const uint32_t a2 = Ps[(r0 + g) * QP + ks + tig + 4];
            const uint32_t a3 = Ps[(r0 + g + 8) * QP + ks + tig + 4];
            #pragma unroll
            for (int j = 0; j < 8; ++j) {
                const uint32_t b0 = Vs[(ks + tig) * VP + j * 8 + g];
                const uint32_t b1 = Vs[(ks + tig + 4) * VP + j * 8 + g];
                mma_tf32(oacc[j][0], oacc[j][1], oacc[j][2], oacc[j][3],
                         a0, a1, a2, a3, b0, b1);
            }
        }
        __syncwarp();   // P reads done before next iteration overwrites
    }

    // ---- epilogue
    const float inv0 = 1.0f / l0;
    const float inv1 = 1.0f / l1;
    const int row_g  = b * SEQ + q0 + r0 + g;
    const int row_g8 = row_g + 8;
    #pragma unroll
    for (int j = 0; j < 8; ++j) {
        const int col = h * 64 + j * 8 + 2 * tig;
        *(float2*)&out[(size_t)row_g  * DIM + col] = make_float2(oacc[j][0] * inv0, oacc[j][1] * inv0);
        *(float2*)&out[(size_t)row_g8 * DIM + col] = make_float2(oacc[j][2] * inv1, oacc[j][3] * inv1);
    }
}

// ---------------- launch ----------------
static float* sym_addr(const void* sym) {
    void* p = nullptr;
    cudaGetSymbolAddress(&p, sym);
    return (float*)p;
}

extern "C" void kernel_launch(void* const* d_in, const int* in_sizes, int n_in,
                              void* d_out, int out_size) {
    const float* x     = (const float*)d_in[0];
    const float* ln1w  = (const float*)d_in[1];
    const float* ln1b  = (const float*)d_in[2];
    const float* qkvw  = (const float*)d_in[3];
    const float* qkvb  = (const float*)d_in[4];
    const float* projw = (const float*)d_in[5];
    const float* projb = (const float*)d_in[6];
    const float* ln2w  = (const float*)d_in[7];
    const float* ln2b  = (const float*)d_in[8];
    const float* lin1w = (const float*)d_in[9];
    const float* lin1b = (const float*)d_in[10];
    const float* lin2w = (const float*)d_in[11];
    const float* lin2b = (const float*)d_in[12];
    float* out = (float*)d_out;

    float* xn   = sym_addr(g_xn);
    float* qkvB = sym_addr(g_qkv);
    float* attn = sym_addr(g_attn);
    float* x1   = sym_addr(g_x1);
    float* hB   = sym_addr(g_h);
    float* h1   = sym_addr(g_h1);

    const int flash_smem = FLASH_SMEM_U32 * 4;
    cudaFuncSetAttribute(flash_tc_kernel, cudaFuncAttributeMaxDynamicSharedMemorySize, flash_smem);

    // 1. ln1
    ln_kernel<<<TOK, 256>>>(x, ln1w, ln1b, xn);
    // 2. qkv = xn @ qkv_w + b  (tf32 TC)
    tgemm_kernel<0><<<dim3(3 * DIM / 128, TOK / 128), 256>>>(xn, qkvw, qkvb, nullptr, qkvB, TOK, 3 * DIM, DIM);
    // 3. attention (tf32 TC flash)
    flash_tc_kernel<<<dim3(SEQ / 64, 2 * NHEAD), 128, flash_smem>>>(qkvB, attn);
    // 4. x1 = x + attn @ proj_w + b  (tf32 TC)
    tgemm_kernel<1><<<dim3(DIM / 128, TOK / 128), 256>>>(attn, projw, projb, x, x1, TOK, DIM, DIM);
    // 5. ln2
    ln_kernel<<<TOK, 256>>>(x1, ln2w, ln2b, hB);
    // 6. h1 = gelu(h @ lin1_w + b)  (tf32 TC)
    tgemm_kernel<2><<<dim3(MLPD / 128, TOK / 128), 256>>>(hB, lin1w, lin1b, nullptr, h1, TOK, MLPD, DIM);
    // 7. out = x1 + h1 @ lin2_w + b  (tf32 TC)
    tgemm_kernel<1><<<dim3(DIM / 128, TOK / 128), 256>>>(h1, lin2w, lin2b, x1, out, TOK, DIM, MLPD);
}

// round 5
// speedup vs baseline: 2.8632x; 1.2252x over previous
#include <cuda_runtime.h>
#include <math.h>
#include <stdint.h>

#define DIM 768
#define TOK 4096          // B*N = 2*2048
#define SEQ 2048
#define NHEAD 12
#define HDIM 64
#define MLPD 3072

// ---------------- scratch (static device globals; no allocation) ----------------
__device__ float g_xn[TOK * DIM];
__device__ float g_qkv[TOK * 3 * DIM];
__device__ float g_attn[TOK * DIM];
__device__ float g_x1[TOK * DIM];
__device__ float g_h[TOK * DIM];
__device__ float g_h1[TOK * MLPD];

// ---------------- LayerNorm: one block (256 thr) per row of 768 ----------------
__global__ void ln_kernel(const float* __restrict__ x, const float* __restrict__ w,
                          const float* __restrict__ b, float* __restrict__ y) {
    const int row = blockIdx.x;
    const int tid = threadIdx.x;
    const float* xr = x + (size_t)row * DIM;
    float v0 = xr[tid], v1 = xr[tid + 256], v2 = xr[tid + 512];
    float s  = v0 + v1 + v2;
    float sq = v0 * v0 + v1 * v1 + v2 * v2;
    __shared__ float red0[8], red1[8];
    #pragma unroll
    for (int mm = 16; mm; mm >>= 1) {
        s  += __shfl_xor_sync(0xffffffffu, s,  mm);
        sq += __shfl_xor_sync(0xffffffffu, sq, mm);
    }
    const int wid = tid >> 5, lane = tid & 31;
    if (lane == 0) { red0[wid] = s; red1[wid] = sq; }
    __syncthreads();
    if (wid == 0) {
        s = red0[lane & 7]; sq = red1[lane & 7];
        #pragma unroll
        for (int mm = 4; mm; mm >>= 1) {
            s  += __shfl_xor_sync(0xffffffffu, s,  mm);
            sq += __shfl_xor_sync(0xffffffffu, sq, mm);
        }
        if (lane == 0) { red0[0] = s; red1[0] = sq; }
    }
    __syncthreads();
    s = red0[0]; sq = red1[0];
    const float mu  = s * (1.0f / DIM);
    const float var = sq * (1.0f / DIM) - mu * mu;
    const float r   = rsqrtf(var + 1e-5f);
    float* yr = y + (size_t)row * DIM;
    yr[tid]       = (v0 - mu) * r * w[tid]       + b[tid];
    yr[tid + 256] = (v1 - mu) * r * w[tid + 256] + b[tid + 256];
    yr[tid + 512] = (v2 - mu) * r * w[tid + 512] + b[tid + 512];
}

// ---------------- tf32 helpers ----------------
__device__ __forceinline__ uint32_t f2tf32(float f) {
    uint32_t u;
    asm("cvt.rna.tf32.f32 %0, %1;" : "=r"(u) : "f"(f));
    return u;
}

__device__ __forceinline__ void mma_tf32(float& c0, float& c1, float& c2, float& c3,
                                         uint32_t a0, uint32_t a1, uint32_t a2, uint32_t a3,
                                         uint32_t b0, uint32_t b1) {
    asm volatile(
        "mma.sync.aligned.m16n8k8.row.col.f32.tf32.tf32.f32 "
        "{%0,%1,%2,%3}, {%4,%5,%6,%7}, {%8,%9}, {%0,%1,%2,%3};"
        : "+f"(c0), "+f"(c1), "+f"(c2), "+f"(c3)
        : "r"(a0), "r"(a1), "r"(a2), "r"(a3), "r"(b0), "r"(b1));
}

// ---------------- tf32 tensor-core GEMM 128x128, BK=16, double-buffered ----------------
// Fragment-packed smem: A fragments load as LDS.128, B fragments as LDS.64.
// Af layout: [buf][ (ks8*8 + mtile)*128 + swz(lane)*4 + reg ],  swz(lane)=lane^(lane>>2)
//   reg: 0=(g,tig) 1=(g+8,tig) 2=(g,tig+4) 3=(g+8,tig+4)  for m-tile rows, k within 8
// Bf layout: [buf][ (ks8*16 + ntile)*64 + (lane^(ntile&15))*2 + sel ]
//   sel: 0=B(k=tig, n) 1=B(k=tig+4, n),  lane=g*4+tig with n = ntile*8+g
// EPI: 0 = bias, 1 = bias + residual, 2 = bias + exact GELU
template <int EPI>
__global__ __launch_bounds__(256, 2)
void tgemm_kernel(const float* __restrict__ A, const float* __restrict__ W,
                  const float* __restrict__ bias, const float* __restrict__ res,
                  float* __restrict__ C, int M, int N, int K) {
    __shared__ __align__(16) uint32_t Af[2][2048];
    __shared__ __align__(16) uint32_t Bf[2][2048];

    const int tid = threadIdx.x;
    const int bm = blockIdx.y * 128, bn = blockIdx.x * 128;
    const int wid = tid >> 5, lane = tid & 31;
    const int warp_m = wid & 1, warp_n = wid >> 1;       // 2 x 4
    const int g = lane >> 2, tig = lane & 3;

    // ---- global load indices (same coverage as before)
    const int ar = tid >> 2, ac4 = tid & 3;              // A rows ar, ar+64; k-cols ac4*4..+3
    const int brr = tid >> 5;                             // B k-rows brr, brr+8
    const int bcg = (tid & 31) * 4;                       // B n-cols bcg..bcg+3
    const float* Ap = A + (size_t)(bm + ar) * K + ac4 * 4;
    const float* Bp = W + (size_t)brr * N + bn + bcg;

    // ---- writer fragment-store indices
    const int ks8a = ac4 >> 1, sela = ac4 & 1;
    const int mt0 = ar >> 4, row16 = ar & 15;
    const int ga = row16 & 7, halfa = row16 >> 3;
    const int rega = halfa + 2 * sela;
    int aswz[4];
    #pragma unroll
    for (int e = 0; e < 4; ++e)
        aswz[e] = ((((ga * 4 + e) ^ ga) & 31) << 2) + rega;
    const int abase0 = (ks8a * 8 + mt0) * 128;
    const int abase1 = (ks8a * 8 + mt0 + 4) * 128;

    const int tigb = brr & 3, selb = brr >> 2;
    const int ntw = bcg >> 3, g0 = bcg & 7;
    int bswz[4];
    #pragma unroll
    for (int e = 0; e < 4; ++e)
        bswz[e] = (((((g0 + e) * 4 + tigb) ^ (ntw & 15)) & 31) << 1) + selb;
    const int bbase0 = ntw * 64;
    const int bbase1 = bbase0 + 1024;

    // ---- reader offsets (precomputed, XOR swizzles folded in)
    const int lswA = ((lane ^ ((lane >> 2) & 7)) << 2);
    const int aof = warp_m * 4 * 128 + lswA;              // + ks8*1024 + i*128
    int bof[4];
    #pragma unroll
    for (int j = 0; j < 4; ++j) {
        const int nt = warp_n * 4 + j;
        bof[j] = nt * 64 + ((lane ^ (nt & 15)) << 1);     // + ks8*1024
    }

    float acc[4][4][4];
    #pragma unroll
    for (int i = 0; i < 4; ++i)
        #pragma unroll
        for (int j = 0; j < 4; ++j)
            #pragma unroll
            for (int c = 0; c < 4; ++c) acc[i][j][c] = 0.0f;

    // ---- prologue: stage buffer 0
    {
        float4 a0 = *(const float4*)Ap;
        float4 a1 = *(const float4*)(Ap + (size_t)64 * K);
        float4 b0 = *(const float4*)Bp;
        float4 b1 = *(const float4*)(Bp + (size_t)8 * N);
        Af[0][abase0 + aswz[0]] = f2tf32(a0.x);
        Af[0][abase0 + aswz[1]] = f2tf32(a0.y);
        Af[0][abase0 + aswz[2]] = f2tf32(a0.z);
        Af[0][abase0 + aswz[3]] = f2tf32(a0.w);
        Af[0][abase1 + aswz[0]] = f2tf32(a1.x);
        Af[0][abase1 + aswz[1]] = f2tf32(a1.y);
        Af[0][abase1 + aswz[2]] = f2tf32(a1.z);
        Af[0][abase1 + aswz[3]] = f2tf32(a1.w);
        Bf[0][bbase0 + bswz[0]] = f2tf32(b0.x);
        Bf[0][bbase0 + bswz[1]] = f2tf32(b0.y);
        Bf[0][bbase0 + bswz[2]] = f2tf32(b0.z);
        Bf[0][bbase0 + bswz[3]] = f2tf32(b0.w);
        Bf[0][bbase1 + bswz[0]] = f2tf32(b1.x);
        Bf[0][bbase1 + bswz[1]] = f2tf32(b1.y);
        Bf[0][bbase1 + bswz[2]] = f2tf32(b1.z);
        Bf[0][bbase1 + bswz[3]] = f2tf32(b1.w);
    }
    __syncthreads();

    const int nk = K >> 4;    // BK = 16
    for (int kt = 0; kt < nk; ++kt) {
        const int cur = kt & 1;
        float4 pa0, pa1, pb0, pb1;
        const bool more = (kt + 1 < nk);
        if (more) {
            pa0 = *(const float4*)(Ap + (kt + 1) * 16);
            pa1 = *(const float4*)(Ap + (size_t)64 * K + (kt + 1) * 16);
            pb0 = *(const float4*)(Bp + (size_t)(kt + 1) * 16 * N);
            pb1 = *(const float4*)(Bp + (size_t)((kt + 1) * 16 + 8) * N);
        }

        #pragma unroll
        for (int ks8 = 0; ks8 < 2; ++ks8) {
            const uint32_t* afp = &Af[cur][ks8 * 1024 + aof];
            const uint4 f0 = *(const uint4*)(afp);
            const uint4 f1 = *(const uint4*)(afp + 128);
            const uint4 f2 = *(const uint4*)(afp + 256);
            const uint4 f3 = *(const uint4*)(afp + 384);
            const uint32_t* bfp = &Bf[cur][ks8 * 1024];
            const uint2 b0 = *(const uint2*)(bfp + bof[0]);
            const uint2 b1 = *(const uint2*)(bfp + bof[1]);
            const uint2 b2 = *(const uint2*)(bfp + bof[2]);
            const uint2 b3 = *(const uint2*)(bfp + bof[3]);

            #pragma unroll
            for (int j = 0; j < 4; ++j) {
                const uint2 bj = (j == 0) ? b0 : (j == 1) ? b1 : (j == 2) ? b2 : b3;
                mma_tf32(acc[0][j][0], acc[0][j][1], acc[0][j][2], acc[0][j][3],
                         f0.x, f0.y, f0.z, f0.w, bj.x, bj.y);
                mma_tf32(acc[1][j][0], acc[1][j][1], acc[1][j][2], acc[1][j][3],
                         f1.x, f1.y, f1.z, f1.w, bj.x, bj.y);
                mma_tf32(acc[2][j][0], acc[2][j][1], acc[2][j][2], acc[2][j][3],
                         f2.x, f2.y, f2.z, f2.w, bj.x, bj.y);
                mma_tf32(acc[3][j][0], acc[3][j][1], acc[3][j][2], acc[3][j][3],
                         f3.x, f3.y, f3.z, f3.w, bj.x, bj.y);
            }
        }

        if (more) {
            const int nxt = cur ^ 1;
            Af[nxt][abase0 + aswz[0]] = f2tf32(pa0.x);
            Af[nxt][abase0 + aswz[1]] = f2tf32(pa0.y);
            Af[nxt][abase0 + aswz[2]] = f2tf32(pa0.z);
            Af[nxt][abase0 + aswz[3]] = f2tf32(pa0.w);
            Af[nxt][abase1 + aswz[0]] = f2tf32(pa1.x);
            Af[nxt][abase1 + aswz[1]] = f2tf32(pa1.y);
            Af[nxt][abase1 + aswz[2]] = f2tf32(pa1.z);
            Af[nxt][abase1 + aswz[3]] = f2tf32(pa1.w);
            Bf[nxt][bbase0 + bswz[0]] = f2tf32(pb0.x);
            Bf[nxt][bbase0 + bswz[1]] = f2tf32(pb0.y);
            Bf[nxt][bbase0 + bswz[2]] = f2tf32(pb0.z);
            Bf[nxt][bbase0 + bswz[3]] = f2tf32(pb0.w);
            Bf[nxt][bbase1 + bswz[0]] = f2tf32(pb1.x);
            Bf[nxt][bbase1 + bswz[1]] = f2tf32(pb1.y);
            Bf[nxt][bbase1 + bswz[2]] = f2tf32(pb1.z);
            Bf[nxt][bbase1 + bswz[3]] = f2tf32(pb1.w);
        }
        __syncthreads();
    }

    // ---- epilogue: thread owns rows {g, g+8} per m-tile, col pair 2*tig per n-tile
    #pragma unroll
    for (int i = 0; i < 4; ++i) {
        #pragma unroll
        for (int half = 0; half < 2; ++half) {
            const int r = bm + warp_m * 64 + i * 16 + g + half * 8;
            float* Crow = C + (size_t)r * N;
            const float* Rrow = (EPI == 1) ? (res + (size_t)r * N) : nullptr;
            #pragma unroll
            for (int j = 0; j < 4; ++j) {
                const int col = bn + warp_n * 32 + j * 8 + tig * 2;
                float v0 = acc[i][j][half * 2 + 0] + bias[col];
                float v1 = acc[i][j][half * 2 + 1] + bias[col + 1];
                if (EPI == 1) {
                    v0 += Rrow[col];
                    v1 += Rrow[col + 1];
                }
                if (EPI == 2) {
                    v0 = 0.5f * v0 * (1.0f + erff(v0 * 0.70710678118654752f));
                    v1 = 0.5f * v1 * (1.0f + erff(v1 * 0.70710678118654752f));
                }
                *(float2*)&Crow[col] = make_float2(v0, v1);
            }
        }
    }
}

// ---------------- tf32 tensor-core flash attention ----------------
#define QP 68
#define VP 72
#define FLASH_SMEM_U32 (64 * QP /*Q*/ + 64 * QP /*K*/ + 64 * VP /*V*/ + 64 * QP /*P*/)

__global__ __launch_bounds__(128, 3)
void flash_tc_kernel(const float* __restrict__ qkv, float* __restrict__ out) {
    extern __shared__ uint32_t sm[];
    uint32_t* Qs = sm;                 // 64 x QP
    uint32_t* Ks = Qs + 64 * QP;       // 64 x QP
    uint32_t* Vs = Ks + 64 * QP;       // 64 x VP
    uint32_t* Ps = Vs + 64 * VP;       // 64 x QP

    const int tid = threadIdx.x;
    const int wid = tid >> 5, lane = tid & 31;
    const int g = lane >> 2, tig = lane & 3;
    const int bh = blockIdx.y;
    const int b = bh / NHEAD, h = bh % NHEAD;
    const int q0 = blockIdx.x * 64;
    const int r0 = wid * 16;
    const size_t base = (size_t)b * SEQ * (3 * DIM);

    #pragma unroll
    for (int it = 0; it < 8; ++it) {
        const int f = tid + it * 128;
        const int row = f >> 4, c4 = f & 15;
        float4 q = *(const float4*)&qkv[base + (size_t)(q0 + row) * (3 * DIM) + h * 64 + c4 * 4];
        uint32_t* p = &Qs[row * QP + c4 * 4];
        p[0] = f2tf32(q.x); p[1] = f2tf32(q.y); p[2] = f2tf32(q.z); p[3] = f2tf32(q.w);
    }

    float m0 = -1e30f, m1 = -1e30f, l0 = 0.0f, l1 = 0.0f;
    float oacc[8][4];
    #pragma unroll
    for (int j = 0; j < 8; ++j)
        #pragma unroll
        for (int c = 0; c < 4; ++c) oacc[j][c] = 0.0f;

    for (int kt = 0; kt < SEQ / 64; ++kt) {
        __syncthreads();
        #pragma unroll
        for (int it = 0; it < 8; ++it) {
            const int f = tid + it * 128;
            const int row = f >> 4, c4 = f & 15;
            const size_t off = base + (size_t)(kt * 64 + row) * (3 * DIM) + h * 64 + c4 * 4;
            float4 k = *(const float4*)&qkv[off + DIM];
            float4 v = *(const float4*)&qkv[off + 2 * DIM];
            uint32_t* pk = &Ks[row * QP + c4 * 4];
            pk[0] = f2tf32(k.x); pk[1] = f2tf32(k.y); pk[2] = f2tf32(k.z); pk[3] = f2tf32(k.w);
            uint32_t* pv = &Vs[row * VP + c4 * 4];
            pv[0] = f2tf32(v.x); pv[1] = f2tf32(v.y); pv[2] = f2tf32(v.z); pv[3] = f2tf32(v.w);
        }
        __syncthreads();

        float sacc[8][4];
        #pragma unroll
        for (int j = 0; j < 8; ++j)
            #pragma unroll
            for (int c = 0; c < 4; ++c) sacc[j][c] = 0.0f;

        #pragma unroll
        for (int ks = 0; ks < 64; ks += 8) {
            const uint32_t a0 = Qs[(r0 + g) * QP + ks + tig];
            const uint32_t a1 = Qs[(r0 + g + 8) * QP + ks + tig];
            const uint32_t a2 = Qs[(r0 + g) * QP + ks + tig + 4];
            const uint32_t a3 = Qs[(r0 + g + 8) * QP + ks + tig + 4];
            #pragma unroll
            for (int j = 0; j < 8; ++j) {
                const uint32_t b0 = Ks[(j * 8 + g) * QP + ks + tig];
                const uint32_t b1 = Ks[(j * 8 + g) * QP + ks + tig + 4];
                mma_tf32(sacc[j][0], sacc[j][1], sacc[j][2], sacc[j][3],
                         a0, a1, a2, a3, b0, b1);
            }
        }

        float rm0 = -1e30f, rm1 = -1e30f;
        #pragma unroll
        for (int j = 0; j < 8; ++j) {
            sacc[j][0] *= 0.125f; sacc[j][1] *= 0.125f;
            sacc[j][2] *= 0.125f; sacc[j][3] *= 0.125f;
            rm0 = fmaxf(rm0, fmaxf(sacc[j][0], sacc[j][1]));
            rm1 = fmaxf(rm1, fmaxf(sacc[j][2], sacc[j][3]));
        }
        rm0 = fmaxf(rm0, __shfl_xor_sync(0xffffffffu, rm0, 1));
        rm0 = fmaxf(rm0, __shfl_xor_sync(0xffffffffu, rm0, 2));
        rm1 = fmaxf(rm1, __shfl_xor_sync(0xffffffffu, rm1, 1));
        rm1 = fmaxf(rm1, __shfl_xor_sync(0xffffffffu, rm1, 2));

        const float mn0 = fmaxf(m0, rm0);
        const float mn1 = fmaxf(m1, rm1);
        const float alpha0 = __expf(m0 - mn0);
        const float alpha1 = __expf(m1 - mn1);
        m0 = mn0; m1 = mn1;

        float ps0 = 0.0f, ps1 = 0.0f;
        #pragma unroll
        for (int j = 0; j < 8; ++j) {
            sacc[j][0] = __expf(sacc[j][0] - mn0);
            sacc[j][1] = __expf(sacc[j][1] - mn0);
            sacc[j][2] = __expf(sacc[j][2] - mn1);
            sacc[j][3] = __expf(sacc[j][3] - mn1);
            ps0 += sacc[j][0] + sacc[j][1];
            ps1 += sacc[j][2] + sacc[j][3];
        }
        ps0 += __shfl_xor_sync(0xffffffffu, ps0, 1);
        ps0 += __shfl_xor_sync(0xffffffffu, ps0, 2);
        ps1 += __shfl_xor_sync(0xffffffffu, ps1, 1);
        ps1 += __shfl_xor_sync(0xffffffffu, ps1, 2);
        l0 = l0 * alpha0 + ps0;
        l1 = l1 * alpha1 + ps1;

        #pragma unroll
        for (int j = 0; j < 8; ++j) {
            oacc[j][0] *= alpha0; oacc[j][1] *= alpha0;
            oacc[j][2] *= alpha1; oacc[j][3] *= alpha1;
        }

        #pragma unroll
        for (int j = 0; j < 8; ++j) {
            const int col = j * 8 + 2 * tig;
            Ps[(r0 + g) * QP + col]         = f2tf32(sacc[j][0]);
            Ps[(r0 + g) * QP + col + 1]     = f2tf32(sacc[j][1]);
            Ps[(r0 + g + 8) * QP + col]     = f2tf32(sacc[j][2]);
            Ps[(r0 + g + 8) * QP + col + 1] = f2tf32(sacc[j][3]);
        }
        __syncwarp();

        #pragma unroll
        for (int ks = 0; ks < 64; ks += 8) {
            const uint32_t a0 = Ps[(r0 + g) * QP + ks + tig];
            const uint32_t a1 = Ps[(r0 + g + 8) * QP + ks + tig];
            const uint32_t a2 = Ps[(r0 + g) * QP + ks + tig + 4];
            const uint32_t a3 = Ps[(r0 + g + 8) * QP + ks + tig + 4];
            #pragma unroll
            for (int j = 0; j < 8; ++j) {
                const uint32_t b0 = Vs[(ks + tig) * VP + j * 8 + g];
                const uint32_t b1 = Vs[(ks + tig + 4) * VP + j * 8 + g];
                mma_tf32(oacc[j][0], oacc[j][1], oacc[j][2], oacc[j][3],
                         a0, a1, a2, a3, b0, b1);
            }
        }
        __syncwarp();
    }

    const float inv0 = 1.0f / l0;
    const float inv1 = 1.0f / l1;
    const int row_g  = b * SEQ + q0 + r0 + g;
    const int row_g8 = row_g + 8;
    #pragma unroll
    for (int j = 0; j < 8; ++j) {
        const int col = h * 64 + j * 8 + 2 * tig;
        *(float2*)&out[(size_t)row_g  * DIM + col] = make_float2(oacc[j][0] * inv0, oacc[j][1] * inv0);
        *(float2*)&out[(size_t)row_g8 * DIM + col] = make_float2(oacc[j][2] * inv1, oacc[j][3] * inv1);
    }
}

// ---------------- launch ----------------
static float* sym_addr(const void* sym) {
    void* p = nullptr;
    cudaGetSymbolAddress(&p, sym);
    return (float*)p;
}

extern "C" void kernel_launch(void* const* d_in, const int* in_sizes, int n_in,
                              void* d_out, int out_size) {
    const float* x     = (const float*)d_in[0];
    const float* ln1w  = (const float*)d_in[1];
    const float* ln1b  = (const float*)d_in[2];
    const float* qkvw  = (const float*)d_in[3];
    const float* qkvb  = (const float*)d_in[4];
    const float* projw = (const float*)d_in[5];
    const float* projb = (const float*)d_in[6];
    const float* ln2w  = (const float*)d_in[7];
    const float* ln2b  = (const float*)d_in[8];
    const float* lin1w = (const float*)d_in[9];
    const float* lin1b = (const float*)d_in[10];
    const float* lin2w = (const float*)d_in[11];
    const float* lin2b = (const float*)d_in[12];
    float* out = (float*)d_out;

    float* xn   = sym_addr(g_xn);
    float* qkvB = sym_addr(g_qkv);
    float* attn = sym_addr(g_attn);
    float* x1   = sym_addr(g_x1);
    float* hB   = sym_addr(g_h);
    float* h1   = sym_addr(g_h1);

    const int flash_smem = FLASH_SMEM_U32 * 4;
    cudaFuncSetAttribute(flash_tc_kernel, cudaFuncAttributeMaxDynamicSharedMemorySize, flash_smem);

    // 1. ln1
    ln_kernel<<<TOK, 256>>>(x, ln1w, ln1b, xn);
    // 2. qkv = xn @ qkv_w + b  (tf32 TC)
    tgemm_kernel<0><<<dim3(3 * DIM / 128, TOK / 128), 256>>>(xn, qkvw, qkvb, nullptr, qkvB, TOK, 3 * DIM, DIM);
    // 3. attention (tf32 TC flash)
    flash_tc_kernel<<<dim3(SEQ / 64, 2 * NHEAD), 128, flash_smem>>>(qkvB, attn);
    // 4. x1 = x + attn @ proj_w + b  (tf32 TC)
    tgemm_kernel<1><<<dim3(DIM / 128, TOK / 128), 256>>>(attn, projw, projb, x, x1, TOK, DIM, DIM);
    // 5. ln2
    ln_kernel<<<TOK, 256>>>(x1, ln2w, ln2b, hB);
    // 6. h1 = gelu(h @ lin1_w + b)  (tf32 TC)
    tgemm_kernel<2><<<dim3(MLPD / 128, TOK / 128), 256>>>(hB, lin1w, lin1b, nullptr, h1, TOK, MLPD, DIM);
    // 7. out = x1 + h1 @ lin2_w + b  (tf32 TC)
    tgemm_kernel<1><<<dim3(DIM / 128, TOK / 128), 256>>>(h1, lin2w, lin2b, x1, out, TOK, DIM, MLPD);
}

// round 8
// speedup vs baseline: 3.1601x; 1.1037x over previous
#include <cuda_runtime.h>
#include <math.h>
#include <stdint.h>

#define DIM 768
#define TOK 4096          // B*N = 2*2048
#define SEQ 2048
#define NHEAD 12
#define HDIM 64
#define MLPD 3072

// ---------------- scratch (static device globals; no allocation) ----------------
__device__ float g_xn[TOK * DIM];
__device__ float g_qkv[TOK * 3 * DIM];
__device__ float g_attn[TOK * DIM];
__device__ float g_x1[TOK * DIM];
__device__ float g_h[TOK * DIM];
__device__ float g_h1[TOK * MLPD];
__device__ float g_part[4 * TOK * DIM];   // split-K partials for lin2

// ---------------- LayerNorm: one block (256 thr) per row of 768 ----------------
__global__ void ln_kernel(const float* __restrict__ x, const float* __restrict__ w,
                          const float* __restrict__ b, float* __restrict__ y) {
    const int row = blockIdx.x;
    const int tid = threadIdx.x;
    const float* xr = x + (size_t)row * DIM;
    float v0 = xr[tid], v1 = xr[tid + 256], v2 = xr[tid + 512];
    float s  = v0 + v1 + v2;
    float sq = v0 * v0 + v1 * v1 + v2 * v2;
    __shared__ float red0[8], red1[8];
    #pragma unroll
    for (int mm = 16; mm; mm >>= 1) {
        s  += __shfl_xor_sync(0xffffffffu, s,  mm);
        sq += __shfl_xor_sync(0xffffffffu, sq, mm);
    }
    const int wid = tid >> 5, lane = tid & 31;
    if (lane == 0) { red0[wid] = s; red1[wid] = sq; }
    __syncthreads();
    if (wid == 0) {
        s = red0[lane & 7]; sq = red1[lane & 7];
        #pragma unroll
        for (int mm = 4; mm; mm >>= 1) {
            s  += __shfl_xor_sync(0xffffffffu, s,  mm);
            sq += __shfl_xor_sync(0xffffffffu, sq, mm);
        }
        if (lane == 0) { red0[0] = s; red1[0] = sq; }
    }
    __syncthreads();
    s = red0[0]; sq = red1[0];
    const float mu  = s * (1.0f / DIM);
    const float var = sq * (1.0f / DIM) - mu * mu;
    const float r   = rsqrtf(var + 1e-5f);
    float* yr = y + (size_t)row * DIM;
    yr[tid]       = (v0 - mu) * r * w[tid]       + b[tid];
    yr[tid + 256] = (v1 - mu) * r * w[tid + 256] + b[tid + 256];
    yr[tid + 512] = (v2 - mu) * r * w[tid + 512] + b[tid + 512];
}

// ---------------- tf32 helpers ----------------
// mma.tf32 ignores the low 13 mantissa bits of each operand, so raw fp32
// bit patterns are legal tf32 operands (truncation rounding). No cvt needed.
__device__ __forceinline__ uint32_t f2u(float f) { return __float_as_uint(f); }

__device__ __forceinline__ void mma_tf32(float& c0, float& c1, float& c2, float& c3,
                                         uint32_t a0, uint32_t a1, uint32_t a2, uint32_t a3,
                                         uint32_t b0, uint32_t b1) {
    asm volatile(
        "mma.sync.aligned.m16n8k8.row.col.f32.tf32.tf32.f32 "
        "{%0,%1,%2,%3}, {%4,%5,%6,%7}, {%8,%9}, {%0,%1,%2,%3};"
        : "+f"(c0), "+f"(c1), "+f"(c2), "+f"(c3)
        : "r"(a0), "r"(a1), "r"(a2), "r"(a3), "r"(b0), "r"(b1));
}

// ---------------- tf32 tensor-core GEMM 128x128, BK=16, double-buffered ----------------
// Fragment-packed smem: A fragments load as LDS.128, B fragments as LDS.64.
// K = row stride of A (elements); klen = K-extent this launch processes;
// blockIdx.z = split-K slice (z*klen offset into K). EPI 3 writes raw partials
// to C + z*M*N.
// EPI: 0 = bias, 1 = bias + residual, 2 = bias + exact GELU, 3 = raw partial
template <int EPI>
__global__ __launch_bounds__(256, 2)
void tgemm_kernel(const float* __restrict__ A, const float* __restrict__ W,
                  const float* __restrict__ bias, const float* __restrict__ res,
                  float* __restrict__ C, int M, int N, int K, int klen) {
    __shared__ __align__(16) uint32_t Af[2][2048];
    __shared__ __align__(16) uint32_t Bf[2][2048];

    const int tid = threadIdx.x;
    const int bm = blockIdx.y * 128, bn = blockIdx.x * 128;
    const int z = blockIdx.z;
    A += (size_t)z * klen;                // offset within each row
    W += (size_t)z * klen * N;            // offset in k-rows
    if (EPI == 3) C += (size_t)z * M * N;

    const int wid = tid >> 5, lane = tid & 31;
    const int warp_m = wid & 1, warp_n = wid >> 1;       // 2 x 4
    const int g = lane >> 2, tig = lane & 3;

    const int ar = tid >> 2, ac4 = tid & 3;
    const int brr = tid >> 5;
    const int bcg = (tid & 31) * 4;
    const float* Ap = A + (size_t)(bm + ar) * K + ac4 * 4;
    const float* Bp = W + (size_t)brr * N + bn + bcg;

    const int ks8a = ac4 >> 1, sela = ac4 & 1;
    const int mt0 = ar >> 4, row16 = ar & 15;
    const int ga = row16 & 7, halfa = row16 >> 3;
    const int rega = halfa + 2 * sela;
    int aswz[4];
    #pragma unroll
    for (int e = 0; e < 4; ++e)
        aswz[e] = ((((ga * 4 + e) ^ ga) & 31) << 2) + rega;
    const int abase0 = (ks8a * 8 + mt0) * 128;
    const int abase1 = (ks8a * 8 + mt0 + 4) * 128;

    const int tigb = brr & 3, selb = brr >> 2;
    const int ntw = bcg >> 3, g0 = bcg & 7;
    int bswz[4];
    #pragma unroll
    for (int e = 0; e < 4; ++e)
        bswz[e] = (((((g0 + e) * 4 + tigb) ^ (ntw & 15)) & 31) << 1) + selb;
    const int bbase0 = ntw * 64;
    const int bbase1 = bbase0 + 1024;

    const int lswA = ((lane ^ ((lane >> 2) & 7)) << 2);
    const int aof = warp_m * 4 * 128 + lswA;
    int bof[4];
    #pragma unroll
    for (int j = 0; j < 4; ++j) {
        const int nt = warp_n * 4 + j;
        bof[j] = nt * 64 + ((lane ^ (nt & 15)) << 1);
    }

    float acc[4][4][4];
    #pragma unroll
    for (int i = 0; i < 4; ++i)
        #pragma unroll
        for (int j = 0; j < 4; ++j)
            #pragma unroll
            for (int c = 0; c < 4; ++c) acc[i][j][c] = 0.0f;

    {
        float4 a0 = *(const float4*)Ap;
        float4 a1 = *(const float4*)(Ap + (size_t)64 * K);
        float4 b0 = *(const float4*)Bp;
        float4 b1 = *(const float4*)(Bp + (size_t)8 * N);
        Af[0][abase0 + aswz[0]] = f2u(a0.x);
        Af[0][abase0 + aswz[1]] = f2u(a0.y);
        Af[0][abase0 + aswz[2]] = f2u(a0.z);
        Af[0][abase0 + aswz[3]] = f2u(a0.w);
        Af[0][abase1 + aswz[0]] = f2u(a1.x);
        Af[0][abase1 + aswz[1]] = f2u(a1.y);
        Af[0][abase1 + aswz[2]] = f2u(a1.z);
        Af[0][abase1 + aswz[3]] = f2u(a1.w);
        Bf[0][bbase0 + bswz[0]] = f2u(b0.x);
        Bf[0][bbase0 + bswz[1]] = f2u(b0.y);
        Bf[0][bbase0 + bswz[2]] = f2u(b0.z);
        Bf[0][bbase0 + bswz[3]] = f2u(b0.w);
        Bf[0][bbase1 + bswz[0]] = f2u(b1.x);
        Bf[0][bbase1 + bswz[1]] = f2u(b1.y);
        Bf[0][bbase1 + bswz[2]] = f2u(b1.z);
        Bf[0][bbase1 + bswz[3]] = f2u(b1.w);
    }
    __syncthreads();

    const int nk = klen >> 4;    // BK = 16
    for (int kt = 0; kt < nk; ++kt) {
        const int cur = kt & 1;
        float4 pa0, pa1, pb0, pb1;
        const bool more = (kt + 1 < nk);
        if (more) {
            pa0 = *(const float4*)(Ap + (kt + 1) * 16);
            pa1 = *(const float4*)(Ap + (size_t)64 * K + (kt + 1) * 16);
            pb0 = *(const float4*)(Bp + (size_t)(kt + 1) * 16 * N);
            pb1 = *(const float4*)(Bp + (size_t)((kt + 1) * 16 + 8) * N);
        }

        #pragma unroll
        for (int ks8 = 0; ks8 < 2; ++ks8) {
            const uint32_t* afp = &Af[cur][ks8 * 1024 + aof];
            const uint4 f0 = *(const uint4*)(afp);
            const uint4 f1 = *(const uint4*)(afp + 128);
            const uint4 f2 = *(const uint4*)(afp + 256);
            const uint4 f3 = *(const uint4*)(afp + 384);
            const uint32_t* bfp = &Bf[cur][ks8 * 1024];
            const uint2 b0 = *(const uint2*)(bfp + bof[0]);
            const uint2 b1 = *(const uint2*)(bfp + bof[1]);
            const uint2 b2 = *(const uint2*)(bfp + bof[2]);
            const uint2 b3 = *(const uint2*)(bfp + bof[3]);

            #pragma unroll
            for (int j = 0; j < 4; ++j) {
                const uint2 bj = (j == 0) ? b0 : (j == 1) ? b1 : (j == 2) ? b2 : b3;
                mma_tf32(acc[0][j][0], acc[0][j][1], acc[0][j][2], acc[0][j][3],
                         f0.x, f0.y, f0.z, f0.w, bj.x, bj.y);
                mma_tf32(acc[1][j][0], acc[1][j][1], acc[1][j][2], acc[1][j][3],
                         f1.x, f1.y, f1.z, f1.w, bj.x, bj.y);
                mma_tf32(acc[2][j][0], acc[2][j][1], acc[2][j][2], acc[2][j][3],
                         f2.x, f2.y, f2.z, f2.w, bj.x, bj.y);
                mma_tf32(acc[3][j][0], acc[3][j][1], acc[3][j][2], acc[3][j][3],
                         f3.x, f3.y, f3.z, f3.w, bj.x, bj.y);
            }
        }

        if (more) {
            const int nxt = cur ^ 1;
            Af[nxt][abase0 + aswz[0]] = f2u(pa0.x);
            Af[nxt][abase0 + aswz[1]] = f2u(pa0.y);
            Af[nxt][abase0 + aswz[2]] = f2u(pa0.z);
            Af[nxt][abase0 + aswz[3]] = f2u(pa0.w);
            Af[nxt][abase1 + aswz[0]] = f2u(pa1.x);
            Af[nxt][abase1 + aswz[1]] = f2u(pa1.y);
            Af[nxt][abase1 + aswz[2]] = f2u(pa1.z);
            Af[nxt][abase1 + aswz[3]] = f2u(pa1.w);
            Bf[nxt][bbase0 + bswz[0]] = f2u(pb0.x);
            Bf[nxt][bbase0 + bswz[1]] = f2u(pb0.y);
            Bf[nxt][bbase0 + bswz[2]] = f2u(pb0.z);
            Bf[nxt][bbase0 + bswz[3]] = f2u(pb0.w);
            Bf[nxt][bbase1 + bswz[0]] = f2u(pb1.x);
            Bf[nxt][bbase1 + bswz[1]] = f2u(pb1.y);
            Bf[nxt][bbase1 + bswz[2]] = f2u(pb1.z);
            Bf[nxt][bbase1 + bswz[3]] = f2u(pb1.w);
        }
        __syncthreads();
    }

    // ---- epilogue
    #pragma unroll
    for (int i = 0; i < 4; ++i) {
        #pragma unroll
        for (int half = 0; half < 2; ++half) {
            const int r = bm + warp_m * 64 + i * 16 + g + half * 8;
            float* Crow = C + (size_t)r * N;
            const float* Rrow = (EPI == 1) ? (res + (size_t)r * N) : nullptr;
            #pragma unroll
            for (int j = 0; j < 4; ++j) {
                const int col = bn + warp_n * 32 + j * 8 + tig * 2;
                float v0 = acc[i][j][half * 2 + 0];
                float v1 = acc[i][j][half * 2 + 1];
                if (EPI != 3) { v0 += bias[col]; v1 += bias[col + 1]; }
                if (EPI == 1) {
                    v0 += Rrow[col];
                    v1 += Rrow[col + 1];
                }
                if (EPI == 2) {
                    v0 = 0.5f * v0 * (1.0f + erff(v0 * 0.70710678118654752f));
                    v1 = 0.5f * v1 * (1.0f + erff(v1 * 0.70710678118654752f));
                }
                *(float2*)&Crow[col] = make_float2(v0, v1);
            }
        }
    }
}

// ---------------- split-K combine: out = x1 + bias + sum of 4 partials ----------------
__global__ void combine4_kernel(const float* __restrict__ p, const float* __restrict__ x1,
                                const float* __restrict__ bias, float* __restrict__ out) {
    const int i = (blockIdx.x * 256 + threadIdx.x) * 4;
    const int col = i % DIM;
    float4 a = *(const float4*)&p[i];
    float4 b = *(const float4*)&p[(size_t)TOK * DIM + i];
    float4 c = *(const float4*)&p[(size_t)2 * TOK * DIM + i];
    float4 d = *(const float4*)&p[(size_t)3 * TOK * DIM + i];
    float4 r = *(const float4*)&x1[i];
    float4 bb = *(const float4*)&bias[col];
    float4 o;
    o.x = r.x + bb.x + ((a.x + b.x) + (c.x + d.x));
    o.y = r.y + bb.y + ((a.y + b.y) + (c.y + d.y));
    o.z = r.z + bb.z + ((a.z + b.z) + (c.z + d.z));
    o.w = r.w + bb.w + ((a.w + b.w) + (c.w + d.w));
    *(float4*)&out[i] = o;
}

// ---------------- tf32 tensor-core flash attention ----------------
// P aliased into K's buffer (K dead after S-compute) -> smem 53.2KB -> 4 CTAs/SM.
#define QP 68
#define VP 72
#define FLASH_SMEM_U32 (64 * QP /*Q*/ + 64 * QP /*K=P*/ + 64 * VP /*V*/)

__global__ __launch_bounds__(128, 4)
void flash_tc_kernel(const float* __restrict__ qkv, float* __restrict__ out) {
    extern __shared__ uint32_t sm[];
    uint32_t* Qs = sm;                 // 64 x QP
    uint32_t* Ks = Qs + 64 * QP;       // 64 x QP  (becomes P after S-compute)
    uint32_t* Vs = Ks + 64 * QP;       // 64 x VP
    uint32_t* Ps = Ks;                 // alias

    const int tid = threadIdx.x;
    const int wid = tid >> 5, lane = tid & 31;
    const int g = lane >> 2, tig = lane & 3;
    const int bh = blockIdx.y;
    const int b = bh / NHEAD, h = bh % NHEAD;
    const int q0 = blockIdx.x * 64;
    const int r0 = wid * 16;
    const size_t base = (size_t)b * SEQ * (3 * DIM);

    #pragma unroll
    for (int it = 0; it < 8; ++it) {
        const int f = tid + it * 128;
        const int row = f >> 4, c4 = f & 15;
        float4 q = *(const float4*)&qkv[base + (size_t)(q0 + row) * (3 * DIM) + h * 64 + c4 * 4];
        uint32_t* p = &Qs[row * QP + c4 * 4];
        p[0] = f2u(q.x); p[1] = f2u(q.y); p[2] = f2u(q.z); p[3] = f2u(q.w);
    }

    float m0 = -1e30f, m1 = -1e30f, l0 = 0.0f, l1 = 0.0f;
    float oacc[8][4];
    #pragma unroll
    for (int j = 0; j < 8; ++j)
        #pragma unroll
        for (int c = 0; c < 4; ++c) oacc[j][c] = 0.0f;

    for (int kt = 0; kt < SEQ / 64; ++kt) {
        __syncthreads();   // all warps done with P(=Ks) and Vs of previous iter
        #pragma unroll
        for (int it = 0; it < 8; ++it) {
            const int f = tid + it * 128;
            const int row = f >> 4, c4 = f & 15;
            const size_t off = base + (size_t)(kt * 64 + row) * (3 * DIM) + h * 64 + c4 * 4;
            float4 k = *(const float4*)&qkv[off + DIM];
            float4 v = *(const float4*)&qkv[off + 2 * DIM];
            uint32_t* pk = &Ks[row * QP + c4 * 4];
            pk[0] = f2u(k.x); pk[1] = f2u(k.y); pk[2] = f2u(k.z); pk[3] = f2u(k.w);
            uint32_t* pv = &Vs[row * VP + c4 * 4];
            pv[0] = f2u(v.x); pv[1] = f2u(v.y); pv[2] = f2u(v.z); pv[3] = f2u(v.w);
        }
        __syncthreads();

        float sacc[8][4];
        #pragma unroll
        for (int j = 0; j < 8; ++j)
            #pragma unroll
            for (int c = 0; c < 4; ++c) sacc[j][c] = 0.0f;

        #pragma unroll
        for (int ks = 0; ks < 64; ks += 8) {
            const uint32_t a0 = Qs[(r0 + g) * QP + ks + tig];
            const uint32_t a1 = Qs[(r0 + g + 8) * QP + ks + tig];
            const uint32_t a2 = Qs[(r0 + g) * QP + ks + tig + 4];
            const uint32_t a3 = Qs[(r0 + g + 8) * QP + ks + tig + 4];
            #pragma unroll
            for (int j = 0; j < 8; ++j) {
                const uint32_t b0 = Ks[(j * 8 + g) * QP + ks + tig];
                const uint32_t b1 = Ks[(j * 8 + g) * QP + ks + tig + 4];
                mma_tf32(sacc[j][0], sacc[j][1], sacc[j][2], sacc[j][3],
                         a0, a1, a2, a3, b0, b1);
            }
        }

        float rm0 = -1e30f, rm1 = -1e30f;
        #pragma unroll
        for (int j = 0; j < 8; ++j) {
            sacc[j][0] *= 0.125f; sacc[j][1] *= 0.125f;
            sacc[j][2] *= 0.125f; sacc[j][3] *= 0.125f;
            rm0 = fmaxf(rm0, fmaxf(sacc[j][0], sacc[j][1]));
            rm1 = fmaxf(rm1, fmaxf(sacc[j][2], sacc[j][3]));
        }
        rm0 = fmaxf(rm0, __shfl_xor_sync(0xffffffffu, rm0, 1));
        rm0 = fmaxf(rm0, __shfl_xor_sync(0xffffffffu, rm0, 2));
        rm1 = fmaxf(rm1, __shfl_xor_sync(0xffffffffu, rm1, 1));
        rm1 = fmaxf(rm1, __shfl_xor_sync(0xffffffffu, rm1, 2));

        const float mn0 = fmaxf(m0, rm0);
        const float mn1 = fmaxf(m1, rm1);
        const float alpha0 = __expf(m0 - mn0);
        const float alpha1 = __expf(m1 - mn1);
        m0 = mn0; m1 = mn1;

        float ps0 = 0.0f, ps1 = 0.0f;
        #pragma unroll
        for (int j = 0; j < 8; ++j) {
            sacc[j][0] = __expf(sacc[j][0] - mn0);
            sacc[j][1] = __expf(sacc[j][1] - mn0);
            sacc[j][2] = __expf(sacc[j][2] - mn1);
            sacc[j][3] = __expf(sacc[j][3] - mn1);
            ps0 += sacc[j][0] + sacc[j][1];
            ps1 += sacc[j][2] + sacc[j][3];
        }
        ps0 += __shfl_xor_sync(0xffffffffu, ps0, 1);
        ps0 += __shfl_xor_sync(0xffffffffu, ps0, 2);
        ps1 += __shfl_xor_sync(0xffffffffu, ps1, 1);
        ps1 += __shfl_xor_sync(0xffffffffu, ps1, 2);
        l0 = l0 * alpha0 + ps0;
        l1 = l1 * alpha1 + ps1;

        #pragma unroll
        for (int j = 0; j < 8; ++j) {
            oacc[j][0] *= alpha0; oacc[j][1] *= alpha0;
            oacc[j][2] *= alpha1; oacc[j][3] *= alpha1;
        }

        __syncthreads();   // all warps finished reading Ks before P overwrites it
        #pragma unroll
        for (int j = 0; j < 8; ++j) {
            const int col = j * 8 + 2 * tig;
            Ps[(r0 + g) * QP + col]         = f2u(sacc[j][0]);
            Ps[(r0 + g) * QP + col + 1]     = f2u(sacc[j][1]);
            Ps[(r0 + g + 8) * QP + col]     = f2u(sacc[j][2]);
            Ps[(r0 + g + 8) * QP + col + 1] = f2u(sacc[j][3]);
        }
        __syncwarp();      // P rows are warp-private; warp-local ordering suffices

        #pragma unroll
        for (int ks = 0; ks < 64; ks += 8) {
            const uint32_t a0 = Ps[(r0 + g) * QP + ks + tig];
            const uint32_t a1 = Ps[(r0 + g + 8) * QP + ks + tig];
            const uint32_t a2 = Ps[(r0 + g) * QP + ks + tig + 4];
            const uint32_t a3 = Ps[(r0 + g + 8) * QP + ks + tig + 4];
            #pragma unroll
            for (int j = 0; j < 8; ++j) {
                const uint32_t b0 = Vs[(ks + tig) * VP + j * 8 + g];
                const uint32_t b1 = Vs[(ks + tig + 4) * VP + j * 8 + g];
                mma_tf32(oacc[j][0], oacc[j][1], oacc[j][2], oacc[j][3],
                         a0, a1, a2, a3, b0, b1);
            }
        }
    }

    const float inv0 = 1.0f / l0;
    const float inv1 = 1.0f / l1;
    const int row_g  = b * SEQ + q0 + r0 + g;
    const int row_g8 = row_g + 8;
    #pragma unroll
    for (int j = 0; j < 8; ++j) {
        const int col = h * 64 + j * 8 + 2 * tig;
        *(float2*)&out[(size_t)row_g  * DIM + col] = make_float2(oacc[j][0] * inv0, oacc[j][1] * inv0);
        *(float2*)&out[(size_t)row_g8 * DIM + col] = make_float2(oacc[j][2] * inv1, oacc[j][3] * inv1);
    }
}

// ---------------- launch ----------------
static float* sym_addr(const void* sym) {
    void* p = nullptr;
    cudaGetSymbolAddress(&p, sym);
    return (float*)p;
}

extern "C" void kernel_launch(void* const* d_in, const int* in_sizes, int n_in,
                              void* d_out, int out_size) {
    const float* x     = (const float*)d_in[0];
    const float* ln1w  = (const float*)d_in[1];
    const float* ln1b  = (const float*)d_in[2];
    const float* qkvw  = (const float*)d_in[3];
    const float* qkvb  = (const float*)d_in[4];
    const float* projw = (const float*)d_in[5];
    const float* projb = (const float*)d_in[6];
    const float* ln2w  = (const float*)d_in[7];
    const float* ln2b  = (const float*)d_in[8];
    const float* lin1w = (const float*)d_in[9];
    const float* lin1b = (const float*)d_in[10];
    const float* lin2w = (const float*)d_in[11];
    const float* lin2b = (const float*)d_in[12];
    float* out = (float*)d_out;

    float* xn   = sym_addr(g_xn);
    float* qkvB = sym_addr(g_qkv);
    float* attn = sym_addr(g_attn);
    float* x1   = sym_addr(g_x1);
    float* hB   = sym_addr(g_h);
    float* h1   = sym_addr(g_h1);
    float* part = sym_addr(g_part);

    const int flash_smem = FLASH_SMEM_U32 * 4;
    cudaFuncSetAttribute(flash_tc_kernel, cudaFuncAttributeMaxDynamicSharedMemorySize, flash_smem);

    // 1. ln1
    ln_kernel<<<TOK, 256>>>(x, ln1w, ln1b, xn);
    // 2. qkv = xn @ qkv_w + b  (tf32 TC)
    tgemm_kernel<0><<<dim3(3 * DIM / 128, TOK / 128, 1), 256>>>(xn, qkvw, qkvb, nullptr, qkvB, TOK, 3 * DIM, DIM, DIM);
    // 3. attention (tf32 TC flash, 4 CTAs/SM)
    flash_tc_kernel<<<dim3(SEQ / 64, 2 * NHEAD), 128, flash_smem>>>(qkvB, attn);
    // 4. x1 = x + attn @ proj_w + b  (tf32 TC)
    tgemm_kernel<1><<<dim3(DIM / 128, TOK / 128, 1), 256>>>(attn, projw, projb, x, x1, TOK, DIM, DIM, DIM);
    // 5. ln2
    ln_kernel<<<TOK, 256>>>(x1, ln2w, ln2b, hB);
    // 6. h1 = gelu(h @ lin1_w + b)  (tf32 TC)
    tgemm_kernel<2><<<dim3(MLPD / 128, TOK / 128, 1), 256>>>(hB, lin1w, lin1b, nullptr, h1, TOK, MLPD, DIM, DIM);
    // 7a. partials[z] = h1[:, z*768:(z+1)*768] @ lin2_w[z*768:(z+1)*768, :]  (split-K=4)
    tgemm_kernel<3><<<dim3(DIM / 128, TOK / 128, 4), 256>>>(h1, lin2w, nullptr, nullptr, part, TOK, DIM, MLPD, MLPD / 4);
    // 7b. out = x1 + bias + sum partials
    combine4_kernel<<<(TOK * DIM / 4) / 256, 256>>>(part, x1, lin2b, out);
}